// round 14
// baseline (speedup 1.0000x reference)
#include <cuda_runtime.h>
#include <cuda_bf16.h>
#include <math.h>

// Problem constants
#define NN 1024
#define BB 64
#define TT 12
#define DD 16
#define HH 64
#define CC 65
#define LCOLS (BB*CC)   // 4160 = 65*64
#define OG 128
#define OU 64
#define NP2 512         // node pairs
#define K2T 104         // epilogue K pairs
#define XPAD 209        // padded epilogue row

// ---------------- scratch ----------------
__device__ float d_ne_g[TT*NN*DD];
__device__ float d_ne_u[TT*NN*DD];
__device__ float d_Sg[(size_t)TT*NN*NN];
__device__ float d_Su[(size_t)TT*NN*NN];
__device__ float d_h [NN*BB*HH];
__device__ float d_r [NN*BB*HH];
// PACKED bf16 hi/lo planes: [0,512*LCOLS) hi uints [npair][col], lo after
__device__ float d_Xg [(size_t)NN*LCOLS];
__device__ float d_Y1g[(size_t)NN*LCOLS];
__device__ float d_Y2g[(size_t)NN*LCOLS];
__device__ float d_Xu [(size_t)NN*LCOLS];
__device__ float d_Y1u[(size_t)NN*LCOLS];
__device__ float d_Y2u[(size_t)NN*LCOLS];
#define WGSZ ((size_t)NN*K2T*OG)
#define WUSZ ((size_t)NN*K2T*OU)
__device__ unsigned d_Wg[2*WGSZ];
__device__ unsigned d_Wu[2*WUSZ];

// ---------------- helpers ----------------
__device__ __forceinline__ unsigned pack_bf16(float v0, float v1)
{
    __nv_bfloat162 t = __floats2bfloat162_rn(v0, v1);
    return *(unsigned*)&t;
}
__device__ __forceinline__ void split_pack(float v0, float v1, unsigned& hi, unsigned& lo)
{
    __nv_bfloat16 h0 = __float2bfloat16(v0);
    __nv_bfloat16 h1 = __float2bfloat16(v1);
    float r0 = v0 - __bfloat162float(h0);
    float r1 = v1 - __bfloat162float(h1);
    hi = ((unsigned)__bfloat16_as_ushort(h1) << 16) | (unsigned)__bfloat16_as_ushort(h0);
    lo = pack_bf16(r0, r1);
}
__device__ __forceinline__ void unpack2(unsigned h, unsigned l, float& a, float& b)
{
    __nv_bfloat162 hh = *reinterpret_cast<__nv_bfloat162*>(&h);
    __nv_bfloat162 ll = *reinterpret_cast<__nv_bfloat162*>(&l);
    a = __bfloat162float(hh.x) + __bfloat162float(ll.x);
    b = __bfloat162float(hh.y) + __bfloat162float(ll.y);
}
__device__ __forceinline__ void mma_bf16(float& c0, float& c1, float& c2, float& c3,
    unsigned a0, unsigned a1, unsigned a2, unsigned a3, unsigned b0, unsigned b1)
{
    asm volatile("mma.sync.aligned.m16n8k16.row.col.f32.bf16.bf16.f32 "
        "{%0,%1,%2,%3}, {%4,%5,%6,%7}, {%8,%9}, {%0,%1,%2,%3};\n"
        : "+f"(c0), "+f"(c1), "+f"(c2), "+f"(c3)
        : "r"(a0), "r"(a1), "r"(a2), "r"(a3), "r"(b0), "r"(b1));
}

// ---------------- fused zero_h + pack Xg(t=0) ----------------
__global__ void zero_pack0_kernel(const float* __restrict__ x)
{
    int idx = blockIdx.x*blockDim.x + threadIdx.x;
    if (idx < NN*BB*HH) d_h[idx] = 0.f;
    if (idx < NP2*LCOLS) {
        int i = idx / LCOLS;
        int c = idx - i*LCOLS;
        int b = c / CC, cc = c - b*CC;
        unsigned h = 0, l = 0;
        if (cc == 0)
            split_pack(x[(size_t)(b*TT)*NN + 2*i], x[(size_t)(b*TT)*NN + 2*i + 1], h, l);
        unsigned* Xh = (unsigned*)d_Xg;
        Xh[idx] = h;
        Xh[(size_t)NP2*LCOLS + idx] = l;
    }
}

// ---------------- layernormed embeddings, all t ----------------
__global__ void compute_ne_kernel(const float* __restrict__ nodeE,
                                  const float* __restrict__ timeE,
                                  const float* __restrict__ gg, const float* __restrict__ gbeta,
                                  const float* __restrict__ ug, const float* __restrict__ ubeta)
{
    int idx = blockIdx.x*blockDim.x + threadIdx.x;
    if (idx >= TT*NN) return;
    int t = idx >> 10;
    int n = idx & (NN-1);
    float v[DD];
    float mu = 0.f;
#pragma unroll
    for (int d = 0; d < DD; d++) { v[d] = nodeE[n*DD+d] + timeE[t*DD+d]; mu += v[d]; }
    mu *= (1.f/DD);
    float var = 0.f;
#pragma unroll
    for (int d = 0; d < DD; d++) { float dv = v[d]-mu; var += dv*dv; }
    var *= (1.f/DD);
    float inv = 1.f / sqrtf(var + 1e-12f);
#pragma unroll
    for (int d = 0; d < DD; d++) {
        float nv = (v[d]-mu)*inv;
        d_ne_g[idx*DD+d] = nv*gg[d] + gbeta[d];
        d_ne_u[idx*DD+d] = nv*ug[d] + ubeta[d];
    }
}

// ---------------- scores with inline LN: G = ne @ ne^T ----------------
__global__ __launch_bounds__(256) void score_fused_kernel(
    const float* __restrict__ nodeE, const float* __restrict__ timeE,
    const float* __restrict__ gg, const float* __restrict__ gbeta,
    const float* __restrict__ ug, const float* __restrict__ ubeta)
{
    int z = blockIdx.z;
    int which = (z >= TT) ? 1 : 0;
    int t = which ? (z - TT) : z;
    float* __restrict__ G = (which ? d_Su : d_Sg) + (size_t)t*NN*NN;
    const float* lg = which ? ug : gg;
    const float* lb = which ? ubeta : gbeta;
    __shared__ float Rt[DD][132];
    __shared__ float Ct[DD][132];
    int tid = threadIdx.x;
    {
        int isCol = tid >> 7, r = tid & 127;
        int n = (isCol ? blockIdx.x : blockIdx.y)*128 + r;
        float v[DD];
        float mu = 0.f;
#pragma unroll
        for (int d = 0; d < DD; d++) { v[d] = nodeE[n*DD+d] + timeE[t*DD+d]; mu += v[d]; }
        mu *= (1.f/DD);
        float var = 0.f;
#pragma unroll
        for (int d = 0; d < DD; d++) { float dv = v[d]-mu; var += dv*dv; }
        var *= (1.f/DD);
        float inv = 1.f / sqrtf(var + 1e-12f);
#pragma unroll
        for (int d = 0; d < DD; d++) {
            float nv = (v[d]-mu)*inv*lg[d] + lb[d];
            if (isCol) Ct[d][r] = nv; else Rt[d][r] = nv;
        }
    }
    __syncthreads();
    int ty = tid >> 4, tx = tid & 15;
    int r0 = ty*8, c0 = tx*8;
    float acc[8][8];
#pragma unroll
    for (int i = 0; i < 8; i++)
#pragma unroll
        for (int j = 0; j < 8; j++) acc[i][j] = 0.f;
#pragma unroll
    for (int k = 0; k < DD; k++) {
        float rv[8], cv[8];
        *(float4*)&rv[0] = *(const float4*)&Rt[k][r0];
        *(float4*)&rv[4] = *(const float4*)&Rt[k][r0+4];
        *(float4*)&cv[0] = *(const float4*)&Ct[k][c0];
        *(float4*)&cv[4] = *(const float4*)&Ct[k][c0+4];
#pragma unroll
        for (int i = 0; i < 8; i++)
#pragma unroll
            for (int j = 0; j < 8; j++) acc[i][j] += rv[i]*cv[j];
    }
#pragma unroll
    for (int i = 0; i < 8; i++) {
        float* gp = G + (size_t)(blockIdx.y*128 + r0 + i)*NN + blockIdx.x*128 + c0;
        *(float4*)gp     = make_float4(acc[i][0], acc[i][1], acc[i][2], acc[i][3]);
        *(float4*)(gp+4) = make_float4(acc[i][4], acc[i][5], acc[i][6], acc[i][7]);
    }
}

// ---------------- row softmax, output packed bf16 hi/lo (in-place) ----------------
__global__ __launch_bounds__(256) void softmax_kernel()
{
    int which = blockIdx.z, t = blockIdx.y;
    float* S = (which ? d_Su : d_Sg) + (size_t)t*NN*NN;
    int warp = threadIdx.x >> 5, lane = threadIdx.x & 31;
    int row = blockIdx.x*8 + warp;
    float4* p = (float4*)(S + (size_t)row*NN);
    float4 v[8];
    float mx = -1e30f;
#pragma unroll
    for (int i = 0; i < 8; i++) {
        v[i] = p[lane + i*32];
        mx = fmaxf(mx, fmaxf(fmaxf(v[i].x, v[i].y), fmaxf(v[i].z, v[i].w)));
    }
#pragma unroll
    for (int o = 16; o > 0; o >>= 1) mx = fmaxf(mx, __shfl_xor_sync(0xffffffffu, mx, o));
    float sum = 0.f;
#pragma unroll
    for (int i = 0; i < 8; i++) {
        v[i].x = __expf(v[i].x - mx); v[i].y = __expf(v[i].y - mx);
        v[i].z = __expf(v[i].z - mx); v[i].w = __expf(v[i].w - mx);
        sum += v[i].x + v[i].y + v[i].z + v[i].w;
    }
#pragma unroll
    for (int o = 16; o > 0; o >>= 1) sum += __shfl_xor_sync(0xffffffffu, sum, o);
    float inv = 1.f / sum;
    unsigned* ur = (unsigned*)(S + (size_t)row*NN);
#pragma unroll
    for (int i = 0; i < 8; i++) {
        float a = v[i].x*inv, b = v[i].y*inv, c = v[i].z*inv, d = v[i].w*inv;
        unsigned h0, l0, h1, l1;
        split_pack(a, b, h0, l0);
        split_pack(c, d, h1, l1);
        int j0 = 2*(lane + i*32);
        ur[j0]       = h0; ur[j0+1]       = h1;
        ur[512 + j0] = l0; ur[512 + j0+1] = l1;
    }
}

// ---------------- bf16x3 GEMM: 128x64 tile, 128 threads, 3 CTAs/SM ----------------
__device__ __forceinline__ const float* gemm_src(int id)
{
    switch (id) {
        case 0: return d_Xg;  case 1: return d_Y1g; case 2: return d_Y2g;
        case 3: return d_Xu;  case 4: return d_Y1u; default: return d_Y2u;
    }
}
__device__ __forceinline__ float* gemm_dst(int id)
{
    switch (id) {
        case 1: return d_Y1g; case 2: return d_Y2g;
        case 4: return d_Y1u; default: return d_Y2u;
    }
}

#define ARS 12   // A smem row stride (8 k2 + 4 pad); mod32 pattern conflict-free
#define BRS 72   // B smem k2 stride (64 cols + 8 pad)

__global__ __launch_bounds__(128, 3) void mma_gemm3(int su, int t, int bsel, int csel)
{
    __shared__ unsigned AhS[2][128*ARS];
    __shared__ unsigned AlS[2][128*ARS];
    __shared__ unsigned BhS[2][8*BRS];
    __shared__ unsigned BlS[2][8*BRS];

    const unsigned* Apk = (const unsigned*)((su ? d_Su : d_Sg) + (size_t)t*NN*NN);
    const unsigned* Bgh = (const unsigned*)gemm_src(bsel);
    const unsigned* Bgl = Bgh + (size_t)NP2*LCOLS;
    unsigned* Cgh = (unsigned*)gemm_dst(csel);
    unsigned* Cgl = Cgh + (size_t)NP2*LCOLS;

    int tid = threadIdx.x, warp = tid >> 5, lane = tid & 31;
    int wm = (warp >> 1)*64, wn = (warp & 1)*32;
    int grp = lane >> 2, tig = lane & 3;

    // A staging: thread tid owns row tid (8 k2 words hi + 8 lo per chunk)
    const unsigned* ApH = Apk + (size_t)(blockIdx.y*128 + tid)*1024;
    // B staging: 8 k2 rows x 16 col-quads
    int bK2 = tid >> 4, bC4 = (tid & 15) << 2;
    int colbase = blockIdx.x*64 + bC4;      // LCOLS = 65*64: always in-bounds

    float acc[4][4][4];
#pragma unroll
    for (int i = 0; i < 4; i++)
#pragma unroll
        for (int j = 0; j < 4; j++)
#pragma unroll
            for (int c = 0; c < 4; c++) acc[i][j][c] = 0.f;

    // ---- prologue: stage chunk 0 ----
    {
        uint4 h0 = *(const uint4*)(ApH + 0);
        uint4 h1 = *(const uint4*)(ApH + 4);
        uint4 l0 = *(const uint4*)(ApH + 512);
        uint4 l1 = *(const uint4*)(ApH + 516);
        *(uint4*)&AhS[0][tid*ARS]     = h0;
        *(uint4*)&AhS[0][tid*ARS + 4] = h1;
        *(uint4*)&AlS[0][tid*ARS]     = l0;
        *(uint4*)&AlS[0][tid*ARS + 4] = l1;
        size_t brow = (size_t)bK2*LCOLS + colbase;
        *(uint4*)&BhS[0][bK2*BRS + bC4] = *(const uint4*)(Bgh + brow);
        *(uint4*)&BlS[0][bK2*BRS + bC4] = *(const uint4*)(Bgl + brow);
    }
    __syncthreads();

    int buf = 0;
    for (int k0 = 0; k0 < 1024; k0 += 16) {
        bool pf = (k0 + 16) < 1024;
        uint4 ph0, ph1, pl0, pl1, pbh, pbl;
        if (pf) {
            int k2g = (k0 + 16) >> 1;
            ph0 = *(const uint4*)(ApH + k2g);
            ph1 = *(const uint4*)(ApH + k2g + 4);
            pl0 = *(const uint4*)(ApH + 512 + k2g);
            pl1 = *(const uint4*)(ApH + 516 + k2g);
            size_t brow = (size_t)(k2g + bK2)*LCOLS + colbase;
            pbh = *(const uint4*)(Bgh + brow);
            pbl = *(const uint4*)(Bgl + brow);
        }
        const unsigned* AhB = AhS[buf];
        const unsigned* AlB = AlS[buf];
        const unsigned* BhB = BhS[buf];
        const unsigned* BlB = BlS[buf];

        unsigned bh[4][2], bl[4][2];
#pragma unroll
        for (int nt = 0; nt < 4; nt++) {
            int o = wn + nt*8 + grp;
            bh[nt][0] = BhB[tig*BRS + o];     bh[nt][1] = BhB[(tig+4)*BRS + o];
            bl[nt][0] = BlB[tig*BRS + o];     bl[nt][1] = BlB[(tig+4)*BRS + o];
        }
#pragma unroll
        for (int mt = 0; mt < 4; mt++) {
            int m = wm + mt*16;
            unsigned ah0 = AhB[(m+grp)*ARS   + tig];
            unsigned ah1 = AhB[(m+grp+8)*ARS + tig];
            unsigned ah2 = AhB[(m+grp)*ARS   + tig+4];
            unsigned ah3 = AhB[(m+grp+8)*ARS + tig+4];
            unsigned al0 = AlB[(m+grp)*ARS   + tig];
            unsigned al1 = AlB[(m+grp+8)*ARS + tig];
            unsigned al2 = AlB[(m+grp)*ARS   + tig+4];
            unsigned al3 = AlB[(m+grp+8)*ARS + tig+4];
#pragma unroll
            for (int nt = 0; nt < 4; nt++) {
                mma_bf16(acc[mt][nt][0], acc[mt][nt][1], acc[mt][nt][2], acc[mt][nt][3],
                         ah0, ah1, ah2, ah3, bh[nt][0], bh[nt][1]);
                mma_bf16(acc[mt][nt][0], acc[mt][nt][1], acc[mt][nt][2], acc[mt][nt][3],
                         ah0, ah1, ah2, ah3, bl[nt][0], bl[nt][1]);
                mma_bf16(acc[mt][nt][0], acc[mt][nt][1], acc[mt][nt][2], acc[mt][nt][3],
                         al0, al1, al2, al3, bh[nt][0], bh[nt][1]);
            }
        }
        if (pf) {
            int nb = buf ^ 1;
            *(uint4*)&AhS[nb][tid*ARS]     = ph0;
            *(uint4*)&AhS[nb][tid*ARS + 4] = ph1;
            *(uint4*)&AlS[nb][tid*ARS]     = pl0;
            *(uint4*)&AlS[nb][tid*ARS + 4] = pl1;
            *(uint4*)&BhS[nb][bK2*BRS + bC4] = pbh;
            *(uint4*)&BlS[nb][bK2*BRS + bC4] = pbl;
            __syncthreads();
            buf = nb;
        }
    }

    // ---- epilogue: pack row pairs via shfl, write hi/lo planes ----
#pragma unroll
    for (int mt = 0; mt < 4; mt++) {
        int rowbase = blockIdx.y*128 + wm + mt*16;
#pragma unroll
        for (int nt = 0; nt < 4; nt++) {
            float c0 = acc[mt][nt][0], c1 = acc[mt][nt][1];
            float c2 = acc[mt][nt][2], c3 = acc[mt][nt][3];
            float p0 = __shfl_xor_sync(0xffffffffu, c0, 4);
            float p1 = __shfl_xor_sync(0xffffffffu, c1, 4);
            float p2 = __shfl_xor_sync(0xffffffffu, c2, 4);
            float p3 = __shfl_xor_sync(0xffffffffu, c3, 4);
            unsigned h0, l0, h1, l1;
            int k2;
            if (!(grp & 1)) {
                split_pack(c0, p0, h0, l0);
                split_pack(c1, p1, h1, l1);
                k2 = (rowbase + grp) >> 1;
            } else {
                split_pack(p2, c2, h0, l0);
                split_pack(p3, c3, h1, l1);
                k2 = (rowbase + 7 + grp) >> 1;
            }
            int col0 = blockIdx.x*64 + wn + nt*8 + tig*2;
            *(uint2*)&Cgh[(size_t)k2*LCOLS + col0] = make_uint2(h0, h1);
            *(uint2*)&Cgl[(size_t)k2*LCOLS + col0] = make_uint2(l0, l1);
        }
    }
}

// ---------------- per-node weight banks (r2-split over blockIdx.y) ----------------
__global__ __launch_bounds__(256) void wgen_gate(const float* __restrict__ gW, int t)
{
    __shared__ float ne8[8][16];
    int tid = threadIdx.x;
    int n0 = blockIdx.x*8;
    int r2base = blockIdx.y*26;            // K2T = 104 = 4*26
    if (tid < 128) {
        int n = tid >> 4, d = tid & 15;
        ne8[n][d] = d_ne_g[(size_t)(t*NN + n0 + n)*DD + d];
    }
    __syncthreads();
    int o = tid & 127, half = tid >> 7;
    for (int r2 = r2base + half; r2 < r2base + 26; r2 += 2) {
        int kg0 = 2*r2, kg1 = kg0 + 1;
        float g0[DD], g1[DD];
        if (kg0 < 195) {
            int s = kg0/65, i = kg0 - s*65;
            const float* gp = gW + (size_t)(s*CC + i)*OG + o;
#pragma unroll
            for (int d = 0; d < DD; d++) g0[d] = gp[(size_t)d*(3*CC*OG)];
        } else {
#pragma unroll
            for (int d = 0; d < DD; d++) g0[d] = 0.f;
        }
        if (kg1 < 195) {
            int s = kg1/65, i = kg1 - s*65;
            const float* gp = gW + (size_t)(s*CC + i)*OG + o;
#pragma unroll
            for (int d = 0; d < DD; d++) g1[d] = gp[(size_t)d*(3*CC*OG)];
        } else {
#pragma unroll
            for (int d = 0; d < DD; d++) g1[d] = 0.f;
        }
#pragma unroll
        for (int n = 0; n < 8; n++) {
            float w0 = 0.f, w1 = 0.f;
#pragma unroll
            for (int d = 0; d < DD; d++) {
                float nv = ne8[n][d];
                w0 += nv*g0[d]; w1 += nv*g1[d];
            }
            unsigned h, l;
            split_pack(w0, w1, h, l);
            size_t a = ((size_t)(n0+n)*K2T + r2)*OG + o;
            d_Wg[a] = h;
            d_Wg[WGSZ + a] = l;
        }
    }
}

__global__ __launch_bounds__(256) void wgen_update(const float* __restrict__ uW, int t)
{
    __shared__ float ne8[8][16];
    int tid = threadIdx.x;
    int n0 = blockIdx.x*8;
    int r2base = blockIdx.y*26;
    if (tid < 128) {
        int n = tid >> 4, d = tid & 15;
        ne8[n][d] = d_ne_u[(size_t)(t*NN + n0 + n)*DD + d];
    }
    __syncthreads();
    int o = tid & 63, q = tid >> 6;
    for (int r2 = r2base + q; r2 < r2base + 26; r2 += 4) {
        int kg0 = 2*r2, kg1 = kg0 + 1;
        float g0[DD], g1[DD];
        if (kg0 < 195) {
            int s = kg0/65, i = kg0 - s*65;
            const float* gp = uW + (size_t)(s*CC + i)*OU + o;
#pragma unroll
            for (int d = 0; d < DD; d++) g0[d] = gp[(size_t)d*(3*CC*OU)];
        } else {
#pragma unroll
            for (int d = 0; d < DD; d++) g0[d] = 0.f;
        }
        if (kg1 < 195) {
            int s = kg1/65, i = kg1 - s*65;
            const float* gp = uW + (size_t)(s*CC + i)*OU + o;
#pragma unroll
            for (int d = 0; d < DD; d++) g1[d] = gp[(size_t)d*(3*CC*OU)];
        } else {
#pragma unroll
            for (int d = 0; d < DD; d++) g1[d] = 0.f;
        }
#pragma unroll
        for (int n = 0; n < 8; n++) {
            float w0 = 0.f, w1 = 0.f;
#pragma unroll
            for (int d = 0; d < DD; d++) {
                float nv = ne8[n][d];
                w0 += nv*g0[d]; w1 += nv*g1[d];
            }
            unsigned h, l;
            split_pack(w0, w1, h, l);
            size_t a = ((size_t)(n0+n)*K2T + r2)*OU + o;
            d_Wu[a] = h;
            d_Wu[WUSZ + a] = l;
        }
    }
}

// ============ GCN epilogues: 2 nodes x 32 batches / block, 256 threads ============
#define GATE_SMEM (2*32*XPAD*4 + 2*8*136*4*2 + 2*128*4 + 2*16*4)   // 72064
#define UPD_SMEM  (2*32*XPAD*4 + 2*8*72*4*2  + 2*64*4  + 2*16*4)   // 63360

__global__ __launch_bounds__(256, 3) void gate_epi_mma(
    const float* __restrict__ gb, const float* __restrict__ x, int t)
{
    extern __shared__ char smem[];
    float* xraw = (float*)smem;                                  // [2nd][32b][XPAD]
    unsigned* WhB = (unsigned*)(smem + 2*32*XPAD*4);             // [2nd][8][136]
    unsigned* WlB = WhB + 2*8*136;
    float* sbias  = (float*)(WlB + 2*8*136);                     // [2][128]
    float* nes    = sbias + 2*128;                               // [2][16]

    int tid = threadIdx.x;
    int ip = blockIdx.x;
    int bh = blockIdx.y;
    int n0 = ip*2;
    int bbase = bh*32;

    const unsigned* Xh  = (const unsigned*)d_Xg;  const unsigned* Xl  = Xh  + (size_t)NP2*LCOLS;
    const unsigned* Y1h = (const unsigned*)d_Y1g; const unsigned* Y1l = Y1h + (size_t)NP2*LCOLS;
    const unsigned* Y2h = (const unsigned*)d_Y2g; const unsigned* Y2l = Y2h + (size_t)NP2*LCOLS;

    for (int e = tid; e < 32*CC; e += 256) {
        int bl = e / CC, i = e - (e/CC)*CC;
        size_t off = (size_t)ip*LCOLS + (bbase + bl)*CC + i;
        float x0, x1, y10, y11, y20, y21;
        unpack2(Xh[off],  Xl[off],  x0,  x1);
        unpack2(Y1h[off], Y1l[off], y10, y11);
        unpack2(Y2h[off], Y2l[off], y20, y21);
        int base = bl*XPAD + i;
        xraw[base]       = x0;
        xraw[base + 65]  = y10;
        xraw[base + 130] = 2.f*y20 - x0;
        xraw[32*XPAD + base]       = x1;
        xraw[32*XPAD + base + 65]  = y11;
        xraw[32*XPAD + base + 130] = 2.f*y21 - x1;
    }
    for (int idx = tid; idx < 2*32*14; idx += 256) {
        int nd = idx / 448;
        int r = idx - nd*448;
        int bl = r / 14, k = r - bl*14;
        xraw[nd*32*XPAD + bl*XPAD + 195 + k] = 0.f;
    }
    if (tid < 32) {
        int nd = tid >> 4, d = tid & 15;
        nes[nd*16 + d] = d_ne_g[(size_t)(t*NN + n0 + nd)*DD + d];
    }
    __syncthreads();
    {
        int nd = tid >> 7, o = tid & 127;
        float s = 0.f;
#pragma unroll
        for (int d = 0; d < DD; d++) s += nes[nd*16 + d]*gb[d*OG + o];
        sbias[nd*128 + o] = s;
    }

    int wid = tid >> 5, lane = tid & 31;
    int nd = wid >> 2, w4 = wid & 3;
    int wn = w4*32;
    int grp = lane >> 2, tig = lane & 3;
    const float* xr = xraw + nd*32*XPAD;
    const unsigned* Wh = WhB + nd*1088;
    const unsigned* Wl = WlB + nd*1088;

    float acc[2][4][4];
#pragma unroll
    for (int i = 0; i < 2; i++)
#pragma unroll
        for (int j = 0; j < 4; j++)
#pragma unroll
            for (int c = 0; c < 4; c++) acc[i][j][c] = 0.f;

    for (int ch = 0; ch < 13; ch++) {
#pragma unroll
        for (int rep = 0; rep < 2; rep++) {
            int slot = tid + rep*256;
            int snd = slot >> 8, sr2 = (slot >> 5) & 7, so4 = (slot & 31) << 2;
            size_t a = ((size_t)(n0 + snd)*K2T + ch*8 + sr2)*OG + so4;
            *(uint4*)&WhB[snd*1088 + sr2*136 + so4] = *(const uint4*)&d_Wg[a];
            *(uint4*)&WlB[snd*1088 + sr2*136 + so4] = *(const uint4*)&d_Wg[WGSZ + a];
        }
        __syncthreads();

        unsigned bhf[4][2], blf[4][2];
#pragma unroll
        for (int nt = 0; nt < 4; nt++) {
            int o = wn + nt*8 + grp;
            bhf[nt][0] = Wh[tig*136 + o];     bhf[nt][1] = Wh[(tig+4)*136 + o];
            blf[nt][0] = Wl[tig*136 + o];     blf[nt][1] = Wl[(tig+4)*136 + o];
        }
        int kgA = ch*16 + 2*tig;
#pragma unroll
        for (int mt = 0; mt < 2; mt++) {
            int b0 = mt*16 + grp, b1 = b0 + 8;
            const float* r0 = xr + b0*XPAD;
            const float* r1 = xr + b1*XPAD;
            unsigned ah0, al0, ah1, al1, ah2, al2, ah3, al3;
            split_pack(r0[kgA],   r0[kgA+1], ah0, al0);
            split_pack(r1[kgA],   r1[kgA+1], ah1, al1);
            split_pack(r0[kgA+8], r0[kgA+9], ah2, al2);
            split_pack(r1[kgA+8], r1[kgA+9], ah3, al3);
#pragma unroll
            for (int nt = 0; nt < 4; nt++) {
                mma_bf16(acc[mt][nt][0], acc[mt][nt][1], acc[mt][nt][2], acc[mt][nt][3],
                         ah0, ah1, ah2, ah3, bhf[nt][0], bhf[nt][1]);
                mma_bf16(acc[mt][nt][0], acc[mt][nt][1], acc[mt][nt][2], acc[mt][nt][3],
                         ah0, ah1, ah2, ah3, blf[nt][0], blf[nt][1]);
                mma_bf16(acc[mt][nt][0], acc[mt][nt][1], acc[mt][nt][2], acc[mt][nt][3],
                         al0, al1, al2, al3, bhf[nt][0], bhf[nt][1]);
            }
        }
        __syncthreads();
    }

    // finalize: sigmoid; z -> zh smem ; r -> d_r
    float* zh = xraw;   // reuse: [2nd][32][64]
    int n = n0 + nd;
#pragma unroll
    for (int mt = 0; mt < 2; mt++) {
#pragma unroll
        for (int nt = 0; nt < 4; nt++) {
            int o0 = wn + nt*8 + tig*2;
#pragma unroll
            for (int c = 0; c < 4; c++) {
                int bl = mt*16 + grp + ((c >> 1) ? 8 : 0);
                int b = bbase + bl;
                int o = o0 + (c & 1);
                float v = 1.f/(1.f + __expf(-(acc[mt][nt][c] + sbias[nd*128 + o])));
                if (o < HH) {
                    float hv = d_h[(size_t)(n*BB + b)*HH + o];
                    zh[nd*2048 + bl*64 + o] = v*hv;
                } else {
                    d_r[(size_t)(n*BB + b)*HH + (o - HH)] = v;
                }
            }
        }
    }
    __syncthreads();

    unsigned* Xuh = (unsigned*)d_Xu;
    unsigned* Xul = Xuh + (size_t)NP2*LCOLS;
    for (int idx = tid; idx < 2048; idx += 256) {
        int bl = idx >> 6, o = idx & 63;
        unsigned h, l;
        split_pack(zh[idx], zh[2048 + idx], h, l);
        Xuh[(size_t)ip*LCOLS + (bbase + bl)*CC + 1 + o] = h;
        Xul[(size_t)ip*LCOLS + (bbase + bl)*CC + 1 + o] = l;
    }
    if (tid < 32) {
        int b = bbase + tid;
        unsigned h, l;
        split_pack(x[(size_t)(b*TT + t)*NN + n0], x[(size_t)(b*TT + t)*NN + n0 + 1], h, l);
        Xuh[(size_t)ip*LCOLS + b*CC] = h;
        Xul[(size_t)ip*LCOLS + b*CC] = l;
    }
}

__global__ __launch_bounds__(256, 3) void update_epi_mma(
    const float* __restrict__ ub,
    float* __restrict__ out, const float* __restrict__ x, int t)
{
    extern __shared__ char smem[];
    float* xraw = (float*)smem;                                  // [2nd][32b][XPAD]
    unsigned* WhB = (unsigned*)(smem + 2*32*XPAD*4);             // [2nd][8][72]
    unsigned* WlB = WhB + 2*8*72;
    float* sbias  = (float*)(WlB + 2*8*72);                      // [2][64]
    float* nes    = sbias + 2*64;                                // [2][16]

    int tid = threadIdx.x;
    int ip = blockIdx.x;
    int bh = blockIdx.y;
    int n0 = ip*2;
    int bbase = bh*32;

    const unsigned* Xh  = (const unsigned*)d_Xu;  const unsigned* Xl  = Xh  + (size_t)NP2*LCOLS;
    const unsigned* Y1h = (const unsigned*)d_Y1u; const unsigned* Y1l = Y1h + (size_t)NP2*LCOLS;
    const unsigned* Y2h = (const unsigned*)d_Y2u; const unsigned* Y2l = Y2h + (size_t)NP2*LCOLS;

    for (int e = tid; e < 32*CC; e += 256) {
        int bl = e / CC, i = e - (e/CC)*CC;
        size_t off = (size_t)ip*LCOLS + (bbase + bl)*CC + i;
        float x0, x1, y10, y11, y20, y21;
        unpack2(Xh[off],  Xl[off],  x0,  x1);
        unpack2(Y1h[off], Y1l[off], y10, y11);
        unpack2(Y2h[off], Y2l[off], y20, y21);
        int base = bl*XPAD + i;
        xraw[base]       = x0;
        xraw[base + 65]  = y10;
        xraw[base + 130] = 2.f*y20 - x0;
        xraw[32*XPAD + base]       = x1;
        xraw[32*XPAD + base + 65]  = y11;
        xraw[32*XPAD + base + 130] = 2.f*y21 - x1;
    }
    for (int idx = tid; idx < 2*32*14; idx += 256) {
        int nd = idx / 448;
        int r = idx - nd*448;
        int bl = r / 14, k = r - bl*14;
        xraw[nd*32*XPAD + bl*XPAD + 195 + k] = 0.f;
    }
    if (tid < 32) {
        int nd = tid >> 4, d = tid & 15;
        nes[nd*16 + d] = d_ne_u[(size_t)(t*NN + n0 + nd)*DD + d];
    }
    __syncthreads();
    if (tid < 128) {
        int nd = tid >> 6, o = tid & 63;
        float s = 0.f;
#pragma unroll
        for (int d = 0; d < DD; d++) s += nes[nd*16 + d]*ub[d*OU + o];
        sbias[nd*64 + o] = s;
    }

    int wid = tid >> 5, lane = tid & 31;
    int nd = wid >> 2, w4 = wid & 3;
    int wn = w4*16;
    int grp = lane >> 2, tig = lane & 3;
    const float* xr = xraw + nd*32*XPAD;
    const unsigned* Wh = WhB + nd*576;
    const unsigned* Wl = WlB + nd*576;

    float acc[2][2][4];
#pragma unroll
    for (int i = 0; i < 2; i++)
#pragma unroll
        for (int j = 0; j < 2; j++)
#pragma unroll
            for (int c = 0; c < 4; c++) acc[i][j][c] = 0.f;

    for (int ch = 0; ch < 13; ch++) {
        {
            int snd = tid >> 7, sr2 = (tid >> 4) & 7, so4 = (tid & 15) << 2;
            size_t a = ((size_t)(n0 + snd)*K2T + ch*8 + sr2)*OU + so4;
            *(uint4*)&WhB[snd*576 + sr2*72 + so4] = *(const uint4*)&d_Wu[a];
            *(uint4*)&WlB[snd*576 + sr2*72 + so4] = *(const uint4*)&d_Wu[WUSZ + a];
        }
        __syncthreads();

        unsigned bhf[2][2], blf[2][2];
#pragma unroll
        for (int nt = 0; nt < 2; nt++) {
            int o = wn + nt*8 + grp;
            bhf[nt][0] = Wh[tig*72 + o];     bhf[nt][1] = Wh[(tig+4)*72 + o];
            blf[nt][0] = Wl[tig*72 + o];     blf[nt][1] = Wl[(tig+4)*72 + o];
        }
        int kgA = ch*16 + 2*tig;
#pragma unroll
        for (int mt = 0; mt < 2; mt++) {
            int b0 = mt*16 + grp, b1 = b0 + 8;
            const float* r0 = xr + b0*XPAD;
            const float* r1 = xr + b1*XPAD;
            unsigned ah0, al0, ah1, al1, ah2, al2, ah3, al3;
            split_pack(r0[kgA],   r0[kgA+1], ah0, al0);
            split_pack(r1[kgA],   r1[kgA+1], ah1, al1);
            split_pack(r0[kgA+8], r0[kgA+9], ah2, al2);
            split_pack(r1[kgA+8], r1[kgA+9], ah3, al3);
#pragma unroll
            for (int nt = 0; nt < 2; nt++) {
                mma_bf16(acc[mt][nt][0], acc[mt][nt][1], acc[mt][nt][2], acc[mt][nt][3],
                         ah0, ah1, ah2, ah3, bhf[nt][0], bhf[nt][1]);
                mma_bf16(acc[mt][nt][0], acc[mt][nt][1], acc[mt][nt][2], acc[mt][nt][3],
                         ah0, ah1, ah2, ah3, blf[nt][0], blf[nt][1]);
                mma_bf16(acc[mt][nt][0], acc[mt][nt][1], acc[mt][nt][2], acc[mt][nt][3],
                         al0, al1, al2, al3, bhf[nt][0], bhf[nt][1]);
            }
        }
        __syncthreads();
    }

    float* zh = xraw;   // reuse: [2nd][32][64]
    int n = n0 + nd;
#pragma unroll
    for (int mt = 0; mt < 2; mt++) {
#pragma unroll
        for (int nt = 0; nt < 2; nt++) {
            int o0 = wn + nt*8 + tig*2;
#pragma unroll
            for (int c = 0; c < 4; c++) {
                int bl = mt*16 + grp + ((c >> 1) ? 8 : 0);
                int b = bbase + bl;
                int o = o0 + (c & 1);
                float hc = tanhf(acc[mt][nt][c] + sbias[nd*64 + o]);
                size_t idx = (size_t)(n*BB + b)*HH + o;
                float hv = d_h[idx];
                float rv = d_r[idx];
                float hn = rv*hv + (1.f - rv)*hc;
                d_h[idx] = hn;
                out[((size_t)(b*TT + t)*NN + n)*HH + o] = hn;
                zh[nd*2048 + bl*64 + o] = hn;
            }
        }
    }
    __syncthreads();

    if (t + 1 < TT) {
        unsigned* Xgh = (unsigned*)d_Xg;
        unsigned* Xgl = Xgh + (size_t)NP2*LCOLS;
        for (int idx = tid; idx < 2048; idx += 256) {
            int bl = idx >> 6, o = idx & 63;
            unsigned h, l;
            split_pack(zh[idx], zh[2048 + idx], h, l);
            Xgh[(size_t)ip*LCOLS + (bbase + bl)*CC + 1 + o] = h;
            Xgl[(size_t)ip*LCOLS + (bbase + bl)*CC + 1 + o] = l;
        }
        if (tid < 32) {
            int b = bbase + tid;
            unsigned h, l;
            split_pack(x[(size_t)(b*TT + t+1)*NN + n0], x[(size_t)(b*TT + t+1)*NN + n0 + 1], h, l);
            Xgh[(size_t)ip*LCOLS + b*CC] = h;
            Xgl[(size_t)ip*LCOLS + b*CC] = l;
        }
    }
}

// ---------------- host launcher ----------------
extern "C" void kernel_launch(void* const* d_in, const int* in_sizes, int n_in,
                              void* d_out, int out_size)
{
    const float *x = nullptr, *nodeE = nullptr, *timeE = nullptr;
    const float *gW = nullptr, *gb = nullptr, *uW = nullptr, *ub = nullptr;
    const float *ln16[4] = {nullptr, nullptr, nullptr, nullptr};
    int nln = 0;
    for (int i = 0; i < n_in; i++) {
        const float* p = (const float*)d_in[i];
        switch (in_sizes[i]) {
            case 786432: x = p; break;
            case 16384:  nodeE = p; break;
            case 192:    timeE = p; break;
            case 399360: gW = p; break;
            case 2048:   gb = p; break;
            case 199680: uW = p; break;
            case 1024:   ub = p; break;
            case 16:     if (nln < 4) ln16[nln++] = p; break;
            default: break;
        }
    }
    const float* glg = ln16[0]; const float* glb = ln16[1];
    const float* ulg = ln16[2]; const float* ulb = ln16[3];
    float* out = (float*)d_out;

    cudaFuncSetAttribute(gate_epi_mma,   cudaFuncAttributeMaxDynamicSharedMemorySize, GATE_SMEM);
    cudaFuncSetAttribute(update_epi_mma, cudaFuncAttributeMaxDynamicSharedMemorySize, UPD_SMEM);

    dim3 egrid(NP2, 2);       // node pairs x batch halves
    dim3 wgrid(NN/8, 4);      // node groups x r2 quarters
    dim3 ggrid(LCOLS/64, NN/128);   // (65, 8) = 520 blocks

    // launch order: slot 4 = mma_gemm3 (ncu capture target)
    zero_pack0_kernel<<<(NN*BB*HH + 255)/256, 256>>>(x);                              // 1
    score_fused_kernel<<<dim3(8, 8, 2*TT), 256>>>(nodeE, timeE, glg, glb, ulg, ulb);  // 2
    softmax_kernel<<<dim3(128, TT, 2), 256>>>();                                       // 3

    for (int t = 0; t < TT; t++) {
        mma_gemm3<<<ggrid, 128>>>(0, t, 0, 1);   // Y1g = Sg @ Xg   (4 at t=0)
        if (t == 0)
            compute_ne_kernel<<<(TT*NN + 255)/256, 256>>>(nodeE, timeE, glg, glb, ulg, ulb);
        wgen_gate<<<wgrid, 256>>>(gW, t);
        mma_gemm3<<<ggrid, 128>>>(0, t, 1, 2);   // Y2g = Sg @ Y1g
        gate_epi_mma<<<egrid, 256, GATE_SMEM>>>(gb, x, t);
        mma_gemm3<<<ggrid, 128>>>(1, t, 3, 4);   // Y1u = Su @ Xu
        wgen_update<<<wgrid, 256>>>(uW, t);
        mma_gemm3<<<ggrid, 128>>>(1, t, 4, 5);   // Y2u = Su @ Y1u
        update_epi_mma<<<egrid, 256, UPD_SMEM>>>(ub, out, x, t);
    }
}

// round 15
// speedup vs baseline: 1.2841x; 1.2841x over previous
#include <cuda_runtime.h>
#include <cuda_bf16.h>
#include <math.h>

// Problem constants
#define NN 1024
#define BB 64
#define TT 12
#define DD 16
#define HH 64
#define CC 65
#define LCOLS (BB*CC)   // 4160
#define OG 128
#define OU 64
#define NP2 512         // node pairs
#define K2T 104         // epilogue K pairs
#define XPAD 209        // padded epilogue row

// ---------------- scratch ----------------
__device__ float d_ne_g[TT*NN*DD];
__device__ float d_ne_u[TT*NN*DD];
__device__ float d_Sg[(size_t)TT*NN*NN];
__device__ float d_Su[(size_t)TT*NN*NN];
__device__ float d_h [NN*BB*HH];
__device__ float d_r [NN*BB*HH];
// PACKED bf16 hi/lo planes: [0,512*LCOLS) hi uints [npair][col], lo after
__device__ float d_Xg [(size_t)NN*LCOLS];
__device__ float d_Y1g[(size_t)NN*LCOLS];
__device__ float d_Y2g[(size_t)NN*LCOLS];
__device__ float d_Xu [(size_t)NN*LCOLS];
__device__ float d_Y1u[(size_t)NN*LCOLS];
__device__ float d_Y2u[(size_t)NN*LCOLS];
#define WGSZ ((size_t)NN*K2T*OG)
#define WUSZ ((size_t)NN*K2T*OU)
__device__ unsigned d_Wg[2*WGSZ];
__device__ unsigned d_Wu[2*WUSZ];

// ---------------- helpers ----------------
__device__ __forceinline__ unsigned pack_bf16(float v0, float v1)
{
    __nv_bfloat162 t = __floats2bfloat162_rn(v0, v1);
    return *(unsigned*)&t;
}
__device__ __forceinline__ void split_pack(float v0, float v1, unsigned& hi, unsigned& lo)
{
    __nv_bfloat16 h0 = __float2bfloat16(v0);
    __nv_bfloat16 h1 = __float2bfloat16(v1);
    float r0 = v0 - __bfloat162float(h0);
    float r1 = v1 - __bfloat162float(h1);
    hi = ((unsigned)__bfloat16_as_ushort(h1) << 16) | (unsigned)__bfloat16_as_ushort(h0);
    lo = pack_bf16(r0, r1);
}
__device__ __forceinline__ void unpack2(unsigned h, unsigned l, float& a, float& b)
{
    __nv_bfloat162 hh = *reinterpret_cast<__nv_bfloat162*>(&h);
    __nv_bfloat162 ll = *reinterpret_cast<__nv_bfloat162*>(&l);
    a = __bfloat162float(hh.x) + __bfloat162float(ll.x);
    b = __bfloat162float(hh.y) + __bfloat162float(ll.y);
}
__device__ __forceinline__ void mma_bf16(float& c0, float& c1, float& c2, float& c3,
    unsigned a0, unsigned a1, unsigned a2, unsigned a3, unsigned b0, unsigned b1)
{
    asm volatile("mma.sync.aligned.m16n8k16.row.col.f32.bf16.bf16.f32 "
        "{%0,%1,%2,%3}, {%4,%5,%6,%7}, {%8,%9}, {%0,%1,%2,%3};\n"
        : "+f"(c0), "+f"(c1), "+f"(c2), "+f"(c3)
        : "r"(a0), "r"(a1), "r"(a2), "r"(a3), "r"(b0), "r"(b1));
}

// ---------------- fused zero_h + pack Xg(t=0) ----------------
__global__ void zero_pack0_kernel(const float* __restrict__ x)
{
    int idx = blockIdx.x*blockDim.x + threadIdx.x;
    if (idx < NN*BB*HH) d_h[idx] = 0.f;
    if (idx < NP2*LCOLS) {
        int i = idx / LCOLS;
        int c = idx - i*LCOLS;
        int b = c / CC, cc = c - b*CC;
        unsigned h = 0, l = 0;
        if (cc == 0)
            split_pack(x[(size_t)(b*TT)*NN + 2*i], x[(size_t)(b*TT)*NN + 2*i + 1], h, l);
        unsigned* Xh = (unsigned*)d_Xg;
        Xh[idx] = h;
        Xh[(size_t)NP2*LCOLS + idx] = l;
    }
}

// ---------------- layernormed embeddings, all t ----------------
__global__ void compute_ne_kernel(const float* __restrict__ nodeE,
                                  const float* __restrict__ timeE,
                                  const float* __restrict__ gg, const float* __restrict__ gbeta,
                                  const float* __restrict__ ug, const float* __restrict__ ubeta)
{
    int idx = blockIdx.x*blockDim.x + threadIdx.x;
    if (idx >= TT*NN) return;
    int t = idx >> 10;
    int n = idx & (NN-1);
    float v[DD];
    float mu = 0.f;
#pragma unroll
    for (int d = 0; d < DD; d++) { v[d] = nodeE[n*DD+d] + timeE[t*DD+d]; mu += v[d]; }
    mu *= (1.f/DD);
    float var = 0.f;
#pragma unroll
    for (int d = 0; d < DD; d++) { float dv = v[d]-mu; var += dv*dv; }
    var *= (1.f/DD);
    float inv = 1.f / sqrtf(var + 1e-12f);
#pragma unroll
    for (int d = 0; d < DD; d++) {
        float nv = (v[d]-mu)*inv;
        d_ne_g[idx*DD+d] = nv*gg[d] + gbeta[d];
        d_ne_u[idx*DD+d] = nv*ug[d] + ubeta[d];
    }
}

// ---------------- scores with inline LN: G = ne @ ne^T ----------------
__global__ __launch_bounds__(256) void score_fused_kernel(
    const float* __restrict__ nodeE, const float* __restrict__ timeE,
    const float* __restrict__ gg, const float* __restrict__ gbeta,
    const float* __restrict__ ug, const float* __restrict__ ubeta)
{
    int z = blockIdx.z;
    int which = (z >= TT) ? 1 : 0;
    int t = which ? (z - TT) : z;
    float* __restrict__ G = (which ? d_Su : d_Sg) + (size_t)t*NN*NN;
    const float* lg = which ? ug : gg;
    const float* lb = which ? ubeta : gbeta;
    __shared__ float Rt[DD][132];
    __shared__ float Ct[DD][132];
    int tid = threadIdx.x;
    {
        int isCol = tid >> 7, r = tid & 127;
        int n = (isCol ? blockIdx.x : blockIdx.y)*128 + r;
        float v[DD];
        float mu = 0.f;
#pragma unroll
        for (int d = 0; d < DD; d++) { v[d] = nodeE[n*DD+d] + timeE[t*DD+d]; mu += v[d]; }
        mu *= (1.f/DD);
        float var = 0.f;
#pragma unroll
        for (int d = 0; d < DD; d++) { float dv = v[d]-mu; var += dv*dv; }
        var *= (1.f/DD);
        float inv = 1.f / sqrtf(var + 1e-12f);
#pragma unroll
        for (int d = 0; d < DD; d++) {
            float nv = (v[d]-mu)*inv*lg[d] + lb[d];
            if (isCol) Ct[d][r] = nv; else Rt[d][r] = nv;
        }
    }
    __syncthreads();
    int ty = tid >> 4, tx = tid & 15;
    int r0 = ty*8, c0 = tx*8;
    float acc[8][8];
#pragma unroll
    for (int i = 0; i < 8; i++)
#pragma unroll
        for (int j = 0; j < 8; j++) acc[i][j] = 0.f;
#pragma unroll
    for (int k = 0; k < DD; k++) {
        float rv[8], cv[8];
        *(float4*)&rv[0] = *(const float4*)&Rt[k][r0];
        *(float4*)&rv[4] = *(const float4*)&Rt[k][r0+4];
        *(float4*)&cv[0] = *(const float4*)&Ct[k][c0];
        *(float4*)&cv[4] = *(const float4*)&Ct[k][c0+4];
#pragma unroll
        for (int i = 0; i < 8; i++)
#pragma unroll
            for (int j = 0; j < 8; j++) acc[i][j] += rv[i]*cv[j];
    }
#pragma unroll
    for (int i = 0; i < 8; i++) {
        float* gp = G + (size_t)(blockIdx.y*128 + r0 + i)*NN + blockIdx.x*128 + c0;
        *(float4*)gp     = make_float4(acc[i][0], acc[i][1], acc[i][2], acc[i][3]);
        *(float4*)(gp+4) = make_float4(acc[i][4], acc[i][5], acc[i][6], acc[i][7]);
    }
}

// ---------------- row softmax, output packed bf16 hi/lo (in-place) ----------------
__global__ __launch_bounds__(256) void softmax_kernel()
{
    int which = blockIdx.z, t = blockIdx.y;
    float* S = (which ? d_Su : d_Sg) + (size_t)t*NN*NN;
    int warp = threadIdx.x >> 5, lane = threadIdx.x & 31;
    int row = blockIdx.x*8 + warp;
    float4* p = (float4*)(S + (size_t)row*NN);
    float4 v[8];
    float mx = -1e30f;
#pragma unroll
    for (int i = 0; i < 8; i++) {
        v[i] = p[lane + i*32];
        mx = fmaxf(mx, fmaxf(fmaxf(v[i].x, v[i].y), fmaxf(v[i].z, v[i].w)));
    }
#pragma unroll
    for (int o = 16; o > 0; o >>= 1) mx = fmaxf(mx, __shfl_xor_sync(0xffffffffu, mx, o));
    float sum = 0.f;
#pragma unroll
    for (int i = 0; i < 8; i++) {
        v[i].x = __expf(v[i].x - mx); v[i].y = __expf(v[i].y - mx);
        v[i].z = __expf(v[i].z - mx); v[i].w = __expf(v[i].w - mx);
        sum += v[i].x + v[i].y + v[i].z + v[i].w;
    }
#pragma unroll
    for (int o = 16; o > 0; o >>= 1) sum += __shfl_xor_sync(0xffffffffu, sum, o);
    float inv = 1.f / sum;
    unsigned* ur = (unsigned*)(S + (size_t)row*NN);
#pragma unroll
    for (int i = 0; i < 8; i++) {
        float a = v[i].x*inv, b = v[i].y*inv, c = v[i].z*inv, d = v[i].w*inv;
        unsigned h0, l0, h1, l1;
        split_pack(a, b, h0, l0);
        split_pack(c, d, h1, l1);
        int j0 = 2*(lane + i*32);
        ur[j0]       = h0; ur[j0+1]       = h1;
        ur[512 + j0] = l0; ur[512 + j0+1] = l1;
    }
}

// ---------------- bf16x3 GEMM: C = S @ B (packed hi/lo), R13 config ----------------
__device__ __forceinline__ const float* gemm_src(int id)
{
    switch (id) {
        case 0: return d_Xg;  case 1: return d_Y1g; case 2: return d_Y2g;
        case 3: return d_Xu;  case 4: return d_Y1u; default: return d_Y2u;
    }
}
__device__ __forceinline__ float* gemm_dst(int id)
{
    switch (id) {
        case 1: return d_Y1g; case 2: return d_Y2g;
        case 4: return d_Y1u; default: return d_Y2u;
    }
}

#define APAD 136
#define BPAD 264
#define GEMM_SMEM ((2*8*APAD*2 + 2*8*BPAD*2)*4)   // 51200 bytes

__global__ __launch_bounds__(256) void mma_gemm2(int su, int t, int bsel, int csel)
{
    extern __shared__ unsigned sm[];
    unsigned* AhS = sm;
    unsigned* AlS = AhS + 2*8*APAD;
    unsigned* BhS = AlS + 2*8*APAD;
    unsigned* BlS = BhS + 2*8*BPAD;

    const unsigned* Apk = (const unsigned*)((su ? d_Su : d_Sg) + (size_t)t*NN*NN);
    const unsigned* Bgh = (const unsigned*)gemm_src(bsel);
    const unsigned* Bgl = Bgh + (size_t)NP2*LCOLS;
    unsigned* Cgh = (unsigned*)gemm_dst(csel);
    unsigned* Cgl = Cgh + (size_t)NP2*LCOLS;

    int tid = threadIdx.x, warp = tid >> 5, lane = tid & 31;
    int wm = (warp >> 2)*64, wn = (warp & 3)*64;
    int grp = lane >> 2, tig = lane & 3;

    int aRow = tid & 127, aHalf = tid >> 7;
    const unsigned* ApH = Apk + (size_t)(blockIdx.y*128 + aRow)*1024 + aHalf*4;

    int bK2 = tid >> 5, bC4 = tid & 31;
    int colr0 = blockIdx.x*256 + bC4*4;
    int colr1 = colr0 + 128;
    bool ok0 = colr0 < LCOLS, ok1 = colr1 < LCOLS;

    float acc[4][8][4];
#pragma unroll
    for (int i = 0; i < 4; i++)
#pragma unroll
        for (int j = 0; j < 8; j++)
#pragma unroll
            for (int c = 0; c < 4; c++) acc[i][j][c] = 0.f;

    const uint4 z4 = make_uint4(0,0,0,0);
    {
        uint4 h = *(const uint4*)ApH;
        uint4 l = *(const uint4*)(ApH + 512);
        int ab = aHalf*4*APAD;
        AhS[ab + 0*APAD + aRow] = h.x; AhS[ab + 1*APAD + aRow] = h.y;
        AhS[ab + 2*APAD + aRow] = h.z; AhS[ab + 3*APAD + aRow] = h.w;
        AlS[ab + 0*APAD + aRow] = l.x; AlS[ab + 1*APAD + aRow] = l.y;
        AlS[ab + 2*APAD + aRow] = l.z; AlS[ab + 3*APAD + aRow] = l.w;
        size_t brow = (size_t)bK2*LCOLS;
        uint4 b0h = ok0 ? *(const uint4*)(Bgh + brow + colr0) : z4;
        uint4 b1h = ok1 ? *(const uint4*)(Bgh + brow + colr1) : z4;
        uint4 b0l = ok0 ? *(const uint4*)(Bgl + brow + colr0) : z4;
        uint4 b1l = ok1 ? *(const uint4*)(Bgl + brow + colr1) : z4;
        int bb = bK2*BPAD;
        *(uint4*)&BhS[bb + bC4*4]       = b0h;
        *(uint4*)&BhS[bb + 128 + bC4*4] = b1h;
        *(uint4*)&BlS[bb + bC4*4]       = b0l;
        *(uint4*)&BlS[bb + 128 + bC4*4] = b1l;
    }
    __syncthreads();

    int buf = 0;
    for (int k0 = 0; k0 < 1024; k0 += 16) {
        bool pf = (k0 + 16) < 1024;
        uint4 ph, pl, pb0h, pb1h, pb0l, pb1l;
        if (pf) {
            int k2g = (k0 + 16) >> 1;
            ph = *(const uint4*)(ApH + k2g);
            pl = *(const uint4*)(ApH + 512 + k2g);
            size_t brow = (size_t)(k2g + bK2)*LCOLS;
            pb0h = ok0 ? *(const uint4*)(Bgh + brow + colr0) : z4;
            pb1h = ok1 ? *(const uint4*)(Bgh + brow + colr1) : z4;
            pb0l = ok0 ? *(const uint4*)(Bgl + brow + colr0) : z4;
            pb1l = ok1 ? *(const uint4*)(Bgl + brow + colr1) : z4;
        }
        const unsigned* AhB = AhS + buf*8*APAD;
        const unsigned* AlB = AlS + buf*8*APAD;
        const unsigned* BhB = BhS + buf*8*BPAD;
        const unsigned* BlB = BlS + buf*8*BPAD;

        unsigned bh[8][2], bl[8][2];
#pragma unroll
        for (int nt = 0; nt < 8; nt++) {
            int o = wn + nt*8 + grp;
            bh[nt][0] = BhB[tig*BPAD + o];     bh[nt][1] = BhB[(tig+4)*BPAD + o];
            bl[nt][0] = BlB[tig*BPAD + o];     bl[nt][1] = BlB[(tig+4)*BPAD + o];
        }
#pragma unroll
        for (int mt = 0; mt < 4; mt++) {
            int m = wm + mt*16;
            unsigned ah0 = AhB[tig*APAD + m+grp];
            unsigned ah1 = AhB[tig*APAD + m+grp+8];
            unsigned ah2 = AhB[(tig+4)*APAD + m+grp];
            unsigned ah3 = AhB[(tig+4)*APAD + m+grp+8];
            unsigned al0 = AlB[tig*APAD + m+grp];
            unsigned al1 = AlB[tig*APAD + m+grp+8];
            unsigned al2 = AlB[(tig+4)*APAD + m+grp];
            unsigned al3 = AlB[(tig+4)*APAD + m+grp+8];
#pragma unroll
            for (int nt = 0; nt < 8; nt++) {
                mma_bf16(acc[mt][nt][0], acc[mt][nt][1], acc[mt][nt][2], acc[mt][nt][3],
                         ah0, ah1, ah2, ah3, bh[nt][0], bh[nt][1]);
                mma_bf16(acc[mt][nt][0], acc[mt][nt][1], acc[mt][nt][2], acc[mt][nt][3],
                         ah0, ah1, ah2, ah3, bl[nt][0], bl[nt][1]);
                mma_bf16(acc[mt][nt][0], acc[mt][nt][1], acc[mt][nt][2], acc[mt][nt][3],
                         al0, al1, al2, al3, bh[nt][0], bh[nt][1]);
            }
        }
        if (pf) {
            int nb = buf ^ 1;
            int ab = nb*8*APAD + aHalf*4*APAD;
            AhS[ab + 0*APAD + aRow] = ph.x; AhS[ab + 1*APAD + aRow] = ph.y;
            AhS[ab + 2*APAD + aRow] = ph.z; AhS[ab + 3*APAD + aRow] = ph.w;
            AlS[ab + 0*APAD + aRow] = pl.x; AlS[ab + 1*APAD + aRow] = pl.y;
            AlS[ab + 2*APAD + aRow] = pl.z; AlS[ab + 3*APAD + aRow] = pl.w;
            int bb = nb*8*BPAD + bK2*BPAD;
            *(uint4*)&BhS[bb + bC4*4]       = pb0h;
            *(uint4*)&BhS[bb + 128 + bC4*4] = pb1h;
            *(uint4*)&BlS[bb + bC4*4]       = pb0l;
            *(uint4*)&BlS[bb + 128 + bC4*4] = pb1l;
            __syncthreads();
            buf = nb;
        }
    }

#pragma unroll
    for (int mt = 0; mt < 4; mt++) {
        int rowbase = blockIdx.y*128 + wm + mt*16;
#pragma unroll
        for (int nt = 0; nt < 8; nt++) {
            float c0 = acc[mt][nt][0], c1 = acc[mt][nt][1];
            float c2 = acc[mt][nt][2], c3 = acc[mt][nt][3];
            float p0 = __shfl_xor_sync(0xffffffffu, c0, 4);
            float p1 = __shfl_xor_sync(0xffffffffu, c1, 4);
            float p2 = __shfl_xor_sync(0xffffffffu, c2, 4);
            float p3 = __shfl_xor_sync(0xffffffffu, c3, 4);
            unsigned h0, l0, h1, l1;
            int k2;
            if (!(grp & 1)) {
                split_pack(c0, p0, h0, l0);
                split_pack(c1, p1, h1, l1);
                k2 = (rowbase + grp) >> 1;
            } else {
                split_pack(p2, c2, h0, l0);
                split_pack(p3, c3, h1, l1);
                k2 = (rowbase + 7 + grp) >> 1;
            }
            int col0 = blockIdx.x*256 + wn + nt*8 + tig*2;
            if (col0 < LCOLS) {
                *(uint2*)&Cgh[(size_t)k2*LCOLS + col0] = make_uint2(h0, h1);
                *(uint2*)&Cgl[(size_t)k2*LCOLS + col0] = make_uint2(l0, l1);
            }
        }
    }
}

// ---------------- fused per-node weight banks (gate z=0, update z=1) ----------------
__global__ __launch_bounds__(256) void wgen_both(const float* __restrict__ gW,
                                                 const float* __restrict__ uW, int t)
{
    __shared__ float ne8[8][16];
    int tid = threadIdx.x;
    int n0 = blockIdx.x*8;
    int r2base = blockIdx.y*26;            // K2T = 104 = 4*26
    int isUpd = blockIdx.z;
    const float* neb = isUpd ? d_ne_u : d_ne_g;
    if (tid < 128) {
        int n = tid >> 4, d = tid & 15;
        ne8[n][d] = neb[(size_t)(t*NN + n0 + n)*DD + d];
    }
    __syncthreads();
    if (!isUpd) {
        int o = tid & 127, half = tid >> 7;
        for (int r2 = r2base + half; r2 < r2base + 26; r2 += 2) {
            int kg0 = 2*r2, kg1 = kg0 + 1;
            float g0[DD], g1[DD];
            if (kg0 < 195) {
                int s = kg0/65, i = kg0 - s*65;
                const float* gp = gW + (size_t)(s*CC + i)*OG + o;
#pragma unroll
                for (int d = 0; d < DD; d++) g0[d] = gp[(size_t)d*(3*CC*OG)];
            } else {
#pragma unroll
                for (int d = 0; d < DD; d++) g0[d] = 0.f;
            }
            if (kg1 < 195) {
                int s = kg1/65, i = kg1 - s*65;
                const float* gp = gW + (size_t)(s*CC + i)*OG + o;
#pragma unroll
                for (int d = 0; d < DD; d++) g1[d] = gp[(size_t)d*(3*CC*OG)];
            } else {
#pragma unroll
                for (int d = 0; d < DD; d++) g1[d] = 0.f;
            }
#pragma unroll
            for (int n = 0; n < 8; n++) {
                float w0 = 0.f, w1 = 0.f;
#pragma unroll
                for (int d = 0; d < DD; d++) {
                    float nv = ne8[n][d];
                    w0 += nv*g0[d]; w1 += nv*g1[d];
                }
                unsigned h, l;
                split_pack(w0, w1, h, l);
                size_t a = ((size_t)(n0+n)*K2T + r2)*OG + o;
                d_Wg[a] = h;
                d_Wg[WGSZ + a] = l;
            }
        }
    } else {
        int o = tid & 63, q = tid >> 6;
        for (int r2 = r2base + q; r2 < r2base + 26; r2 += 4) {
            int kg0 = 2*r2, kg1 = kg0 + 1;
            float g0[DD], g1[DD];
            if (kg0 < 195) {
                int s = kg0/65, i = kg0 - s*65;
                const float* gp = uW + (size_t)(s*CC + i)*OU + o;
#pragma unroll
                for (int d = 0; d < DD; d++) g0[d] = gp[(size_t)d*(3*CC*OU)];
            } else {
#pragma unroll
                for (int d = 0; d < DD; d++) g0[d] = 0.f;
            }
            if (kg1 < 195) {
                int s = kg1/65, i = kg1 - s*65;
                const float* gp = uW + (size_t)(s*CC + i)*OU + o;
#pragma unroll
                for (int d = 0; d < DD; d++) g1[d] = gp[(size_t)d*(3*CC*OU)];
            } else {
#pragma unroll
                for (int d = 0; d < DD; d++) g1[d] = 0.f;
            }
#pragma unroll
            for (int n = 0; n < 8; n++) {
                float w0 = 0.f, w1 = 0.f;
#pragma unroll
                for (int d = 0; d < DD; d++) {
                    float nv = ne8[n][d];
                    w0 += nv*g0[d]; w1 += nv*g1[d];
                }
                unsigned h, l;
                split_pack(w0, w1, h, l);
                size_t a = ((size_t)(n0+n)*K2T + r2)*OU + o;
                d_Wu[a] = h;
                d_Wu[WUSZ + a] = l;
            }
        }
    }
}

// ============ GCN epilogues: 2 nodes x 32 batches / block, 256 threads ============
#define GATE_SMEM (2*32*XPAD*4 + 2*8*136*4*2 + 2*128*4 + 2*16*4)   // 72064
#define UPD_SMEM  (2*32*XPAD*4 + 2*8*72*4*2  + 2*64*4  + 2*16*4)   // 63360

__global__ __launch_bounds__(256, 3) void gate_epi_mma(
    const float* __restrict__ gb, const float* __restrict__ x, int t)
{
    extern __shared__ char smem[];
    float* xraw = (float*)smem;                                  // [2nd][32b][XPAD]
    unsigned* WhB = (unsigned*)(smem + 2*32*XPAD*4);             // [2nd][8][136]
    unsigned* WlB = WhB + 2*8*136;
    float* sbias  = (float*)(WlB + 2*8*136);                     // [2][128]
    float* nes    = sbias + 2*128;                               // [2][16]

    int tid = threadIdx.x;
    int ip = blockIdx.x;
    int bh = blockIdx.y;
    int n0 = ip*2;
    int bbase = bh*32;

    const unsigned* Xh  = (const unsigned*)d_Xg;  const unsigned* Xl  = Xh  + (size_t)NP2*LCOLS;
    const unsigned* Y1h = (const unsigned*)d_Y1g; const unsigned* Y1l = Y1h + (size_t)NP2*LCOLS;
    const unsigned* Y2h = (const unsigned*)d_Y2g; const unsigned* Y2l = Y2h + (size_t)NP2*LCOLS;

    for (int e = tid; e < 32*CC; e += 256) {
        int bl = e / CC, i = e - (e/CC)*CC;
        size_t off = (size_t)ip*LCOLS + (bbase + bl)*CC + i;
        float x0, x1, y10, y11, y20, y21;
        unpack2(Xh[off],  Xl[off],  x0,  x1);
        unpack2(Y1h[off], Y1l[off], y10, y11);
        unpack2(Y2h[off], Y2l[off], y20, y21);
        int base = bl*XPAD + i;
        xraw[base]       = x0;
        xraw[base + 65]  = y10;
        xraw[base + 130] = 2.f*y20 - x0;
        xraw[32*XPAD + base]       = x1;
        xraw[32*XPAD + base + 65]  = y11;
        xraw[32*XPAD + base + 130] = 2.f*y21 - x1;
    }
    for (int idx = tid; idx < 2*32*14; idx += 256) {
        int nd = idx / 448;
        int r = idx - nd*448;
        int bl = r / 14, k = r - bl*14;
        xraw[nd*32*XPAD + bl*XPAD + 195 + k] = 0.f;
    }
    if (tid < 32) {
        int nd = tid >> 4, d = tid & 15;
        nes[nd*16 + d] = d_ne_g[(size_t)(t*NN + n0 + nd)*DD + d];
    }
    __syncthreads();
    {
        int nd = tid >> 7, o = tid & 127;
        float s = 0.f;
#pragma unroll
        for (int d = 0; d < DD; d++) s += nes[nd*16 + d]*gb[d*OG + o];
        sbias[nd*128 + o] = s;
    }

    int wid = tid >> 5, lane = tid & 31;
    int nd = wid >> 2, w4 = wid & 3;
    int wn = w4*32;
    int grp = lane >> 2, tig = lane & 3;
    const float* xr = xraw + nd*32*XPAD;
    const unsigned* Wh = WhB + nd*1088;
    const unsigned* Wl = WlB + nd*1088;

    float acc[2][4][4];
#pragma unroll
    for (int i = 0; i < 2; i++)
#pragma unroll
        for (int j = 0; j < 4; j++)
#pragma unroll
            for (int c = 0; c < 4; c++) acc[i][j][c] = 0.f;

    for (int ch = 0; ch < 13; ch++) {
#pragma unroll
        for (int rep = 0; rep < 2; rep++) {
            int slot = tid + rep*256;
            int snd = slot >> 8, sr2 = (slot >> 5) & 7, so4 = (slot & 31) << 2;
            size_t a = ((size_t)(n0 + snd)*K2T + ch*8 + sr2)*OG + so4;
            *(uint4*)&WhB[snd*1088 + sr2*136 + so4] = *(const uint4*)&d_Wg[a];
            *(uint4*)&WlB[snd*1088 + sr2*136 + so4] = *(const uint4*)&d_Wg[WGSZ + a];
        }
        __syncthreads();

        unsigned bhf[4][2], blf[4][2];
#pragma unroll
        for (int nt = 0; nt < 4; nt++) {
            int o = wn + nt*8 + grp;
            bhf[nt][0] = Wh[tig*136 + o];     bhf[nt][1] = Wh[(tig+4)*136 + o];
            blf[nt][0] = Wl[tig*136 + o];     blf[nt][1] = Wl[(tig+4)*136 + o];
        }
        int kgA = ch*16 + 2*tig;
#pragma unroll
        for (int mt = 0; mt < 2; mt++) {
            int b0 = mt*16 + grp, b1 = b0 + 8;
            const float* r0 = xr + b0*XPAD;
            const float* r1 = xr + b1*XPAD;
            unsigned ah0, al0, ah1, al1, ah2, al2, ah3, al3;
            split_pack(r0[kgA],   r0[kgA+1], ah0, al0);
            split_pack(r1[kgA],   r1[kgA+1], ah1, al1);
            split_pack(r0[kgA+8], r0[kgA+9], ah2, al2);
            split_pack(r1[kgA+8], r1[kgA+9], ah3, al3);
#pragma unroll
            for (int nt = 0; nt < 4; nt++) {
                mma_bf16(acc[mt][nt][0], acc[mt][nt][1], acc[mt][nt][2], acc[mt][nt][3],
                         ah0, ah1, ah2, ah3, bhf[nt][0], bhf[nt][1]);
                mma_bf16(acc[mt][nt][0], acc[mt][nt][1], acc[mt][nt][2], acc[mt][nt][3],
                         ah0, ah1, ah2, ah3, blf[nt][0], blf[nt][1]);
                mma_bf16(acc[mt][nt][0], acc[mt][nt][1], acc[mt][nt][2], acc[mt][nt][3],
                         al0, al1, al2, al3, bhf[nt][0], bhf[nt][1]);
            }
        }
        __syncthreads();
    }

    // finalize: sigmoid; z -> zh smem ; r -> d_r
    float* zh = xraw;   // reuse: [2nd][32][64]
    int n = n0 + nd;
#pragma unroll
    for (int mt = 0; mt < 2; mt++) {
#pragma unroll
        for (int nt = 0; nt < 4; nt++) {
            int o0 = wn + nt*8 + tig*2;
#pragma unroll
            for (int c = 0; c < 4; c++) {
                int bl = mt*16 + grp + ((c >> 1) ? 8 : 0);
                int b = bbase + bl;
                int o = o0 + (c & 1);
                float v = 1.f/(1.f + __expf(-(acc[mt][nt][c] + sbias[nd*128 + o])));
                if (o < HH) {
                    float hv = d_h[(size_t)(n*BB + b)*HH + o];
                    zh[nd*2048 + bl*64 + o] = v*hv;
                } else {
                    d_r[(size_t)(n*BB + b)*HH + (o - HH)] = v;
                }
            }
        }
    }
    __syncthreads();

    unsigned* Xuh = (unsigned*)d_Xu;
    unsigned* Xul = Xuh + (size_t)NP2*LCOLS;
    for (int idx = tid; idx < 2048; idx += 256) {
        int bl = idx >> 6, o = idx & 63;
        unsigned h, l;
        split_pack(zh[idx], zh[2048 + idx], h, l);
        Xuh[(size_t)ip*LCOLS + (bbase + bl)*CC + 1 + o] = h;
        Xul[(size_t)ip*LCOLS + (bbase + bl)*CC + 1 + o] = l;
    }
    if (tid < 32) {
        int b = bbase + tid;
        unsigned h, l;
        split_pack(x[(size_t)(b*TT + t)*NN + n0], x[(size_t)(b*TT + t)*NN + n0 + 1], h, l);
        Xuh[(size_t)ip*LCOLS + b*CC] = h;
        Xul[(size_t)ip*LCOLS + b*CC] = l;
    }
}

__global__ __launch_bounds__(256, 3) void update_epi_mma(
    const float* __restrict__ ub,
    float* __restrict__ out, const float* __restrict__ x, int t)
{
    extern __shared__ char smem[];
    float* xraw = (float*)smem;                                  // [2nd][32b][XPAD]
    unsigned* WhB = (unsigned*)(smem + 2*32*XPAD*4);             // [2nd][8][72]
    unsigned* WlB = WhB + 2*8*72;
    float* sbias  = (float*)(WlB + 2*8*72);                      // [2][64]
    float* nes    = sbias + 2*64;                                // [2][16]

    int tid = threadIdx.x;
    int ip = blockIdx.x;
    int bh = blockIdx.y;
    int n0 = ip*2;
    int bbase = bh*32;

    const unsigned* Xh  = (const unsigned*)d_Xu;  const unsigned* Xl  = Xh  + (size_t)NP2*LCOLS;
    const unsigned* Y1h = (const unsigned*)d_Y1u; const unsigned* Y1l = Y1h + (size_t)NP2*LCOLS;
    const unsigned* Y2h = (const unsigned*)d_Y2u; const unsigned* Y2l = Y2h + (size_t)NP2*LCOLS;

    for (int e = tid; e < 32*CC; e += 256) {
        int bl = e / CC, i = e - (e/CC)*CC;
        size_t off = (size_t)ip*LCOLS + (bbase + bl)*CC + i;
        float x0, x1, y10, y11, y20, y21;
        unpack2(Xh[off],  Xl[off],  x0,  x1);
        unpack2(Y1h[off], Y1l[off], y10, y11);
        unpack2(Y2h[off], Y2l[off], y20, y21);
        int base = bl*XPAD + i;
        xraw[base]       = x0;
        xraw[base + 65]  = y10;
        xraw[base + 130] = 2.f*y20 - x0;
        xraw[32*XPAD + base]       = x1;
        xraw[32*XPAD + base + 65]  = y11;
        xraw[32*XPAD + base + 130] = 2.f*y21 - x1;
    }
    for (int idx = tid; idx < 2*32*14; idx += 256) {
        int nd = idx / 448;
        int r = idx - nd*448;
        int bl = r / 14, k = r - bl*14;
        xraw[nd*32*XPAD + bl*XPAD + 195 + k] = 0.f;
    }
    if (tid < 32) {
        int nd = tid >> 4, d = tid & 15;
        nes[nd*16 + d] = d_ne_u[(size_t)(t*NN + n0 + nd)*DD + d];
    }
    __syncthreads();
    if (tid < 128) {
        int nd = tid >> 6, o = tid & 63;
        float s = 0.f;
#pragma unroll
        for (int d = 0; d < DD; d++) s += nes[nd*16 + d]*ub[d*OU + o];
        sbias[nd*64 + o] = s;
    }

    int wid = tid >> 5, lane = tid & 31;
    int nd = wid >> 2, w4 = wid & 3;
    int wn = w4*16;
    int grp = lane >> 2, tig = lane & 3;
    const float* xr = xraw + nd*32*XPAD;
    const unsigned* Wh = WhB + nd*576;
    const unsigned* Wl = WlB + nd*576;

    float acc[2][2][4];
#pragma unroll
    for (int i = 0; i < 2; i++)
#pragma unroll
        for (int j = 0; j < 2; j++)
#pragma unroll
            for (int c = 0; c < 4; c++) acc[i][j][c] = 0.f;

    for (int ch = 0; ch < 13; ch++) {
        {
            int snd = tid >> 7, sr2 = (tid >> 4) & 7, so4 = (tid & 15) << 2;
            size_t a = ((size_t)(n0 + snd)*K2T + ch*8 + sr2)*OU + so4;
            *(uint4*)&WhB[snd*576 + sr2*72 + so4] = *(const uint4*)&d_Wu[a];
            *(uint4*)&WlB[snd*576 + sr2*72 + so4] = *(const uint4*)&d_Wu[WUSZ + a];
        }
        __syncthreads();

        unsigned bhf[2][2], blf[2][2];
#pragma unroll
        for (int nt = 0; nt < 2; nt++) {
            int o = wn + nt*8 + grp;
            bhf[nt][0] = Wh[tig*72 + o];     bhf[nt][1] = Wh[(tig+4)*72 + o];
            blf[nt][0] = Wl[tig*72 + o];     blf[nt][1] = Wl[(tig+4)*72 + o];
        }
        int kgA = ch*16 + 2*tig;
#pragma unroll
        for (int mt = 0; mt < 2; mt++) {
            int b0 = mt*16 + grp, b1 = b0 + 8;
            const float* r0 = xr + b0*XPAD;
            const float* r1 = xr + b1*XPAD;
            unsigned ah0, al0, ah1, al1, ah2, al2, ah3, al3;
            split_pack(r0[kgA],   r0[kgA+1], ah0, al0);
            split_pack(r1[kgA],   r1[kgA+1], ah1, al1);
            split_pack(r0[kgA+8], r0[kgA+9], ah2, al2);
            split_pack(r1[kgA+8], r1[kgA+9], ah3, al3);
#pragma unroll
            for (int nt = 0; nt < 2; nt++) {
                mma_bf16(acc[mt][nt][0], acc[mt][nt][1], acc[mt][nt][2], acc[mt][nt][3],
                         ah0, ah1, ah2, ah3, bhf[nt][0], bhf[nt][1]);
                mma_bf16(acc[mt][nt][0], acc[mt][nt][1], acc[mt][nt][2], acc[mt][nt][3],
                         ah0, ah1, ah2, ah3, blf[nt][0], blf[nt][1]);
                mma_bf16(acc[mt][nt][0], acc[mt][nt][1], acc[mt][nt][2], acc[mt][nt][3],
                         al0, al1, al2, al3, bhf[nt][0], bhf[nt][1]);
            }
        }
        __syncthreads();
    }

    float* zh = xraw;   // reuse: [2nd][32][64]
    int n = n0 + nd;
#pragma unroll
    for (int mt = 0; mt < 2; mt++) {
#pragma unroll
        for (int nt = 0; nt < 2; nt++) {
            int o0 = wn + nt*8 + tig*2;
#pragma unroll
            for (int c = 0; c < 4; c++) {
                int bl = mt*16 + grp + ((c >> 1) ? 8 : 0);
                int b = bbase + bl;
                int o = o0 + (c & 1);
                float hc = tanhf(acc[mt][nt][c] + sbias[nd*64 + o]);
                size_t idx = (size_t)(n*BB + b)*HH + o;
                float hv = d_h[idx];
                float rv = d_r[idx];
                float hn = rv*hv + (1.f - rv)*hc;
                d_h[idx] = hn;
                out[((size_t)(b*TT + t)*NN + n)*HH + o] = hn;
                zh[nd*2048 + bl*64 + o] = hn;
            }
        }
    }
    __syncthreads();

    if (t + 1 < TT) {
        unsigned* Xgh = (unsigned*)d_Xg;
        unsigned* Xgl = Xgh + (size_t)NP2*LCOLS;
        for (int idx = tid; idx < 2048; idx += 256) {
            int bl = idx >> 6, o = idx & 63;
            unsigned h, l;
            split_pack(zh[idx], zh[2048 + idx], h, l);
            Xgh[(size_t)ip*LCOLS + (bbase + bl)*CC + 1 + o] = h;
            Xgl[(size_t)ip*LCOLS + (bbase + bl)*CC + 1 + o] = l;
        }
        if (tid < 32) {
            int b = bbase + tid;
            unsigned h, l;
            split_pack(x[(size_t)(b*TT + t+1)*NN + n0], x[(size_t)(b*TT + t+1)*NN + n0 + 1], h, l);
            Xgh[(size_t)ip*LCOLS + b*CC] = h;
            Xgl[(size_t)ip*LCOLS + b*CC] = l;
        }
    }
}

// ---------------- host launcher ----------------
extern "C" void kernel_launch(void* const* d_in, const int* in_sizes, int n_in,
                              void* d_out, int out_size)
{
    const float *x = nullptr, *nodeE = nullptr, *timeE = nullptr;
    const float *gW = nullptr, *gb = nullptr, *uW = nullptr, *ub = nullptr;
    const float *ln16[4] = {nullptr, nullptr, nullptr, nullptr};
    int nln = 0;
    for (int i = 0; i < n_in; i++) {
        const float* p = (const float*)d_in[i];
        switch (in_sizes[i]) {
            case 786432: x = p; break;
            case 16384:  nodeE = p; break;
            case 192:    timeE = p; break;
            case 399360: gW = p; break;
            case 2048:   gb = p; break;
            case 199680: uW = p; break;
            case 1024:   ub = p; break;
            case 16:     if (nln < 4) ln16[nln++] = p; break;
            default: break;
        }
    }
    const float* glg = ln16[0]; const float* glb = ln16[1];
    const float* ulg = ln16[2]; const float* ulb = ln16[3];
    float* out = (float*)d_out;

    cudaFuncSetAttribute(mma_gemm2,      cudaFuncAttributeMaxDynamicSharedMemorySize, GEMM_SMEM);
    cudaFuncSetAttribute(gate_epi_mma,   cudaFuncAttributeMaxDynamicSharedMemorySize, GATE_SMEM);
    cudaFuncSetAttribute(update_epi_mma, cudaFuncAttributeMaxDynamicSharedMemorySize, UPD_SMEM);

    dim3 egrid(NP2, 2);          // node pairs x batch halves
    dim3 wgrid(NN/8, 4, 2);      // node groups x r2 quarters x {gate,update}
    dim3 ggrid((LCOLS + 255)/256, NN/128);   // (17, 8) = 136 blocks

    // launch order: slot 4 = mma_gemm2 (ncu capture target)
    zero_pack0_kernel<<<(NN*BB*HH + 255)/256, 256>>>(x);                              // 1
    score_fused_kernel<<<dim3(8, 8, 2*TT), 256>>>(nodeE, timeE, glg, glb, ulg, ulb);  // 2
    softmax_kernel<<<dim3(128, TT, 2), 256>>>();                                       // 3

    for (int t = 0; t < TT; t++) {
        mma_gemm2<<<ggrid, 256, GEMM_SMEM>>>(0, t, 0, 1);   // Y1g = Sg @ Xg   (4 at t=0)
        if (t == 0)
            compute_ne_kernel<<<(TT*NN + 255)/256, 256>>>(nodeE, timeE, glg, glb, ulg, ulb);
        wgen_both<<<wgrid, 256>>>(gW, uW, t);
        mma_gemm2<<<ggrid, 256, GEMM_SMEM>>>(0, t, 1, 2);   // Y2g = Sg @ Y1g
        gate_epi_mma<<<egrid, 256, GATE_SMEM>>>(gb, x, t);
        mma_gemm2<<<ggrid, 256, GEMM_SMEM>>>(1, t, 3, 4);   // Y1u = Su @ Xu
        mma_gemm2<<<ggrid, 256, GEMM_SMEM>>>(1, t, 4, 5);   // Y2u = Su @ Y1u
        update_epi_mma<<<egrid, 256, UPD_SMEM>>>(ub, out, x, t);
    }
}

// round 16
// speedup vs baseline: 1.3124x; 1.0220x over previous
#include <cuda_runtime.h>
#include <cuda_bf16.h>
#include <math.h>

// Problem constants
#define NN 1024
#define BB 64
#define TT 12
#define DD 16
#define HH 64
#define CC 65
#define LCOLS (BB*CC)   // 4160
#define OG 128
#define OU 64
#define NP2 512         // node pairs
#define K2T 104         // epilogue K pairs
#define STR 212         // epilogue ushort row stride (208 kg + 4 pad)

// ---------------- scratch ----------------
__device__ float d_ne_g[TT*NN*DD];
__device__ float d_ne_u[TT*NN*DD];
__device__ float d_Sg[(size_t)TT*NN*NN];
__device__ float d_Su[(size_t)TT*NN*NN];
__device__ float d_h [NN*BB*HH];
__device__ float d_r [NN*BB*HH];
// PACKED bf16 hi/lo planes: [0,512*LCOLS) hi uints [npair][col], lo after
__device__ float d_Xg [(size_t)NN*LCOLS];
__device__ float d_Y1g[(size_t)NN*LCOLS];
__device__ float d_Y2g[(size_t)NN*LCOLS];
__device__ float d_Xu [(size_t)NN*LCOLS];
__device__ float d_Y1u[(size_t)NN*LCOLS];
__device__ float d_Y2u[(size_t)NN*LCOLS];
#define WGSZ ((size_t)NN*K2T*OG)
#define WUSZ ((size_t)NN*K2T*OU)
__device__ unsigned d_Wg[2*WGSZ];
__device__ unsigned d_Wu[2*WUSZ];

// ---------------- helpers ----------------
__device__ __forceinline__ unsigned pack_bf16(float v0, float v1)
{
    __nv_bfloat162 t = __floats2bfloat162_rn(v0, v1);
    return *(unsigned*)&t;
}
__device__ __forceinline__ void split_pack(float v0, float v1, unsigned& hi, unsigned& lo)
{
    __nv_bfloat16 h0 = __float2bfloat16(v0);
    __nv_bfloat16 h1 = __float2bfloat16(v1);
    float r0 = v0 - __bfloat162float(h0);
    float r1 = v1 - __bfloat162float(h1);
    hi = ((unsigned)__bfloat16_as_ushort(h1) << 16) | (unsigned)__bfloat16_as_ushort(h0);
    lo = pack_bf16(r0, r1);
}
__device__ __forceinline__ void unpack2(unsigned h, unsigned l, float& a, float& b)
{
    __nv_bfloat162 hh = *reinterpret_cast<__nv_bfloat162*>(&h);
    __nv_bfloat162 ll = *reinterpret_cast<__nv_bfloat162*>(&l);
    a = __bfloat162float(hh.x) + __bfloat162float(ll.x);
    b = __bfloat162float(hh.y) + __bfloat162float(ll.y);
}
// split one fp32 value into hi/lo bf16 ushorts stored at idx
__device__ __forceinline__ void sp_store(unsigned short* xh, unsigned short* xl, int idx, float v)
{
    __nv_bfloat16 h = __float2bfloat16(v);
    float r = v - __bfloat162float(h);
    xh[idx] = __bfloat16_as_ushort(h);
    xl[idx] = __bfloat16_as_ushort(__float2bfloat16(r));
}
__device__ __forceinline__ void mma_bf16(float& c0, float& c1, float& c2, float& c3,
    unsigned a0, unsigned a1, unsigned a2, unsigned a3, unsigned b0, unsigned b1)
{
    asm volatile("mma.sync.aligned.m16n8k16.row.col.f32.bf16.bf16.f32 "
        "{%0,%1,%2,%3}, {%4,%5,%6,%7}, {%8,%9}, {%0,%1,%2,%3};\n"
        : "+f"(c0), "+f"(c1), "+f"(c2), "+f"(c3)
        : "r"(a0), "r"(a1), "r"(a2), "r"(a3), "r"(b0), "r"(b1));
}

// ---------------- fused zero_h + pack Xg(t=0) ----------------
__global__ void zero_pack0_kernel(const float* __restrict__ x)
{
    int idx = blockIdx.x*blockDim.x + threadIdx.x;
    if (idx < NN*BB*HH) d_h[idx] = 0.f;
    if (idx < NP2*LCOLS) {
        int i = idx / LCOLS;
        int c = idx - i*LCOLS;
        int b = c / CC, cc = c - b*CC;
        unsigned h = 0, l = 0;
        if (cc == 0)
            split_pack(x[(size_t)(b*TT)*NN + 2*i], x[(size_t)(b*TT)*NN + 2*i + 1], h, l);
        unsigned* Xh = (unsigned*)d_Xg;
        Xh[idx] = h;
        Xh[(size_t)NP2*LCOLS + idx] = l;
    }
}

// ---------------- layernormed embeddings, all t ----------------
__global__ void compute_ne_kernel(const float* __restrict__ nodeE,
                                  const float* __restrict__ timeE,
                                  const float* __restrict__ gg, const float* __restrict__ gbeta,
                                  const float* __restrict__ ug, const float* __restrict__ ubeta)
{
    int idx = blockIdx.x*blockDim.x + threadIdx.x;
    if (idx >= TT*NN) return;
    int t = idx >> 10;
    int n = idx & (NN-1);
    float v[DD];
    float mu = 0.f;
#pragma unroll
    for (int d = 0; d < DD; d++) { v[d] = nodeE[n*DD+d] + timeE[t*DD+d]; mu += v[d]; }
    mu *= (1.f/DD);
    float var = 0.f;
#pragma unroll
    for (int d = 0; d < DD; d++) { float dv = v[d]-mu; var += dv*dv; }
    var *= (1.f/DD);
    float inv = 1.f / sqrtf(var + 1e-12f);
#pragma unroll
    for (int d = 0; d < DD; d++) {
        float nv = (v[d]-mu)*inv;
        d_ne_g[idx*DD+d] = nv*gg[d] + gbeta[d];
        d_ne_u[idx*DD+d] = nv*ug[d] + ubeta[d];
    }
}

// ---------------- scores with inline LN: G = ne @ ne^T ----------------
__global__ __launch_bounds__(256) void score_fused_kernel(
    const float* __restrict__ nodeE, const float* __restrict__ timeE,
    const float* __restrict__ gg, const float* __restrict__ gbeta,
    const float* __restrict__ ug, const float* __restrict__ ubeta)
{
    int z = blockIdx.z;
    int which = (z >= TT) ? 1 : 0;
    int t = which ? (z - TT) : z;
    float* __restrict__ G = (which ? d_Su : d_Sg) + (size_t)t*NN*NN;
    const float* lg = which ? ug : gg;
    const float* lb = which ? ubeta : gbeta;
    __shared__ float Rt[DD][132];
    __shared__ float Ct[DD][132];
    int tid = threadIdx.x;
    {
        int isCol = tid >> 7, r = tid & 127;
        int n = (isCol ? blockIdx.x : blockIdx.y)*128 + r;
        float v[DD];
        float mu = 0.f;
#pragma unroll
        for (int d = 0; d < DD; d++) { v[d] = nodeE[n*DD+d] + timeE[t*DD+d]; mu += v[d]; }
        mu *= (1.f/DD);
        float var = 0.f;
#pragma unroll
        for (int d = 0; d < DD; d++) { float dv = v[d]-mu; var += dv*dv; }
        var *= (1.f/DD);
        float inv = 1.f / sqrtf(var + 1e-12f);
#pragma unroll
        for (int d = 0; d < DD; d++) {
            float nv = (v[d]-mu)*inv*lg[d] + lb[d];
            if (isCol) Ct[d][r] = nv; else Rt[d][r] = nv;
        }
    }
    __syncthreads();
    int ty = tid >> 4, tx = tid & 15;
    int r0 = ty*8, c0 = tx*8;
    float acc[8][8];
#pragma unroll
    for (int i = 0; i < 8; i++)
#pragma unroll
        for (int j = 0; j < 8; j++) acc[i][j] = 0.f;
#pragma unroll
    for (int k = 0; k < DD; k++) {
        float rv[8], cv[8];
        *(float4*)&rv[0] = *(const float4*)&Rt[k][r0];
        *(float4*)&rv[4] = *(const float4*)&Rt[k][r0+4];
        *(float4*)&cv[0] = *(const float4*)&Ct[k][c0];
        *(float4*)&cv[4] = *(const float4*)&Ct[k][c0+4];
#pragma unroll
        for (int i = 0; i < 8; i++)
#pragma unroll
            for (int j = 0; j < 8; j++) acc[i][j] += rv[i]*cv[j];
    }
#pragma unroll
    for (int i = 0; i < 8; i++) {
        float* gp = G + (size_t)(blockIdx.y*128 + r0 + i)*NN + blockIdx.x*128 + c0;
        *(float4*)gp     = make_float4(acc[i][0], acc[i][1], acc[i][2], acc[i][3]);
        *(float4*)(gp+4) = make_float4(acc[i][4], acc[i][5], acc[i][6], acc[i][7]);
    }
}

// ---------------- row softmax, output packed bf16 hi/lo (in-place) ----------------
__global__ __launch_bounds__(256) void softmax_kernel()
{
    int which = blockIdx.z, t = blockIdx.y;
    float* S = (which ? d_Su : d_Sg) + (size_t)t*NN*NN;
    int warp = threadIdx.x >> 5, lane = threadIdx.x & 31;
    int row = blockIdx.x*8 + warp;
    float4* p = (float4*)(S + (size_t)row*NN);
    float4 v[8];
    float mx = -1e30f;
#pragma unroll
    for (int i = 0; i < 8; i++) {
        v[i] = p[lane + i*32];
        mx = fmaxf(mx, fmaxf(fmaxf(v[i].x, v[i].y), fmaxf(v[i].z, v[i].w)));
    }
#pragma unroll
    for (int o = 16; o > 0; o >>= 1) mx = fmaxf(mx, __shfl_xor_sync(0xffffffffu, mx, o));
    float sum = 0.f;
#pragma unroll
    for (int i = 0; i < 8; i++) {
        v[i].x = __expf(v[i].x - mx); v[i].y = __expf(v[i].y - mx);
        v[i].z = __expf(v[i].z - mx); v[i].w = __expf(v[i].w - mx);
        sum += v[i].x + v[i].y + v[i].z + v[i].w;
    }
#pragma unroll
    for (int o = 16; o > 0; o >>= 1) sum += __shfl_xor_sync(0xffffffffu, sum, o);
    float inv = 1.f / sum;
    unsigned* ur = (unsigned*)(S + (size_t)row*NN);
#pragma unroll
    for (int i = 0; i < 8; i++) {
        float a = v[i].x*inv, b = v[i].y*inv, c = v[i].z*inv, d = v[i].w*inv;
        unsigned h0, l0, h1, l1;
        split_pack(a, b, h0, l0);
        split_pack(c, d, h1, l1);
        int j0 = 2*(lane + i*32);
        ur[j0]       = h0; ur[j0+1]       = h1;
        ur[512 + j0] = l0; ur[512 + j0+1] = l1;
    }
}

// ---------------- bf16x3 GEMM: C = S @ B (packed hi/lo), R13 config ----------------
__device__ __forceinline__ const float* gemm_src(int id)
{
    switch (id) {
        case 0: return d_Xg;  case 1: return d_Y1g; case 2: return d_Y2g;
        case 3: return d_Xu;  case 4: return d_Y1u; default: return d_Y2u;
    }
}
__device__ __forceinline__ float* gemm_dst(int id)
{
    switch (id) {
        case 1: return d_Y1g; case 2: return d_Y2g;
        case 4: return d_Y1u; default: return d_Y2u;
    }
}

#define APAD 136
#define BPAD 264
#define GEMM_SMEM ((2*8*APAD*2 + 2*8*BPAD*2)*4)   // 51200 bytes

__global__ __launch_bounds__(256) void mma_gemm2(int su, int t, int bsel, int csel)
{
    extern __shared__ unsigned sm[];
    unsigned* AhS = sm;
    unsigned* AlS = AhS + 2*8*APAD;
    unsigned* BhS = AlS + 2*8*APAD;
    unsigned* BlS = BhS + 2*8*BPAD;

    const unsigned* Apk = (const unsigned*)((su ? d_Su : d_Sg) + (size_t)t*NN*NN);
    const unsigned* Bgh = (const unsigned*)gemm_src(bsel);
    const unsigned* Bgl = Bgh + (size_t)NP2*LCOLS;
    unsigned* Cgh = (unsigned*)gemm_dst(csel);
    unsigned* Cgl = Cgh + (size_t)NP2*LCOLS;

    int tid = threadIdx.x, warp = tid >> 5, lane = tid & 31;
    int wm = (warp >> 2)*64, wn = (warp & 3)*64;
    int grp = lane >> 2, tig = lane & 3;

    int aRow = tid & 127, aHalf = tid >> 7;
    const unsigned* ApH = Apk + (size_t)(blockIdx.y*128 + aRow)*1024 + aHalf*4;

    int bK2 = tid >> 5, bC4 = tid & 31;
    int colr0 = blockIdx.x*256 + bC4*4;
    int colr1 = colr0 + 128;
    bool ok0 = colr0 < LCOLS, ok1 = colr1 < LCOLS;

    float acc[4][8][4];
#pragma unroll
    for (int i = 0; i < 4; i++)
#pragma unroll
        for (int j = 0; j < 8; j++)
#pragma unroll
            for (int c = 0; c < 4; c++) acc[i][j][c] = 0.f;

    const uint4 z4 = make_uint4(0,0,0,0);
    {
        uint4 h = *(const uint4*)ApH;
        uint4 l = *(const uint4*)(ApH + 512);
        int ab = aHalf*4*APAD;
        AhS[ab + 0*APAD + aRow] = h.x; AhS[ab + 1*APAD + aRow] = h.y;
        AhS[ab + 2*APAD + aRow] = h.z; AhS[ab + 3*APAD + aRow] = h.w;
        AlS[ab + 0*APAD + aRow] = l.x; AlS[ab + 1*APAD + aRow] = l.y;
        AlS[ab + 2*APAD + aRow] = l.z; AlS[ab + 3*APAD + aRow] = l.w;
        size_t brow = (size_t)bK2*LCOLS;
        uint4 b0h = ok0 ? *(const uint4*)(Bgh + brow + colr0) : z4;
        uint4 b1h = ok1 ? *(const uint4*)(Bgh + brow + colr1) : z4;
        uint4 b0l = ok0 ? *(const uint4*)(Bgl + brow + colr0) : z4;
        uint4 b1l = ok1 ? *(const uint4*)(Bgl + brow + colr1) : z4;
        int bb = bK2*BPAD;
        *(uint4*)&BhS[bb + bC4*4]       = b0h;
        *(uint4*)&BhS[bb + 128 + bC4*4] = b1h;
        *(uint4*)&BlS[bb + bC4*4]       = b0l;
        *(uint4*)&BlS[bb + 128 + bC4*4] = b1l;
    }
    __syncthreads();

    int buf = 0;
    for (int k0 = 0; k0 < 1024; k0 += 16) {
        bool pf = (k0 + 16) < 1024;
        uint4 ph, pl, pb0h, pb1h, pb0l, pb1l;
        if (pf) {
            int k2g = (k0 + 16) >> 1;
            ph = *(const uint4*)(ApH + k2g);
            pl = *(const uint4*)(ApH + 512 + k2g);
            size_t brow = (size_t)(k2g + bK2)*LCOLS;
            pb0h = ok0 ? *(const uint4*)(Bgh + brow + colr0) : z4;
            pb1h = ok1 ? *(const uint4*)(Bgh + brow + colr1) : z4;
            pb0l = ok0 ? *(const uint4*)(Bgl + brow + colr0) : z4;
            pb1l = ok1 ? *(const uint4*)(Bgl + brow + colr1) : z4;
        }
        const unsigned* AhB = AhS + buf*8*APAD;
        const unsigned* AlB = AlS + buf*8*APAD;
        const unsigned* BhB = BhS + buf*8*BPAD;
        const unsigned* BlB = BlS + buf*8*BPAD;

        unsigned bh[8][2], bl[8][2];
#pragma unroll
        for (int nt = 0; nt < 8; nt++) {
            int o = wn + nt*8 + grp;
            bh[nt][0] = BhB[tig*BPAD + o];     bh[nt][1] = BhB[(tig+4)*BPAD + o];
            bl[nt][0] = BlB[tig*BPAD + o];     bl[nt][1] = BlB[(tig+4)*BPAD + o];
        }
#pragma unroll
        for (int mt = 0; mt < 4; mt++) {
            int m = wm + mt*16;
            unsigned ah0 = AhB[tig*APAD + m+grp];
            unsigned ah1 = AhB[tig*APAD + m+grp+8];
            unsigned ah2 = AhB[(tig+4)*APAD + m+grp];
            unsigned ah3 = AhB[(tig+4)*APAD + m+grp+8];
            unsigned al0 = AlB[tig*APAD + m+grp];
            unsigned al1 = AlB[tig*APAD + m+grp+8];
            unsigned al2 = AlB[(tig+4)*APAD + m+grp];
            unsigned al3 = AlB[(tig+4)*APAD + m+grp+8];
#pragma unroll
            for (int nt = 0; nt < 8; nt++) {
                mma_bf16(acc[mt][nt][0], acc[mt][nt][1], acc[mt][nt][2], acc[mt][nt][3],
                         ah0, ah1, ah2, ah3, bh[nt][0], bh[nt][1]);
                mma_bf16(acc[mt][nt][0], acc[mt][nt][1], acc[mt][nt][2], acc[mt][nt][3],
                         ah0, ah1, ah2, ah3, bl[nt][0], bl[nt][1]);
                mma_bf16(acc[mt][nt][0], acc[mt][nt][1], acc[mt][nt][2], acc[mt][nt][3],
                         al0, al1, al2, al3, bh[nt][0], bh[nt][1]);
            }
        }
        if (pf) {
            int nb = buf ^ 1;
            int ab = nb*8*APAD + aHalf*4*APAD;
            AhS[ab + 0*APAD + aRow] = ph.x; AhS[ab + 1*APAD + aRow] = ph.y;
            AhS[ab + 2*APAD + aRow] = ph.z; AhS[ab + 3*APAD + aRow] = ph.w;
            AlS[ab + 0*APAD + aRow] = pl.x; AlS[ab + 1*APAD + aRow] = pl.y;
            AlS[ab + 2*APAD + aRow] = pl.z; AlS[ab + 3*APAD + aRow] = pl.w;
            int bb = nb*8*BPAD + bK2*BPAD;
            *(uint4*)&BhS[bb + bC4*4]       = pb0h;
            *(uint4*)&BhS[bb + 128 + bC4*4] = pb1h;
            *(uint4*)&BlS[bb + bC4*4]       = pb0l;
            *(uint4*)&BlS[bb + 128 + bC4*4] = pb1l;
            __syncthreads();
            buf = nb;
        }
    }

#pragma unroll
    for (int mt = 0; mt < 4; mt++) {
        int rowbase = blockIdx.y*128 + wm + mt*16;
#pragma unroll
        for (int nt = 0; nt < 8; nt++) {
            float c0 = acc[mt][nt][0], c1 = acc[mt][nt][1];
            float c2 = acc[mt][nt][2], c3 = acc[mt][nt][3];
            float p0 = __shfl_xor_sync(0xffffffffu, c0, 4);
            float p1 = __shfl_xor_sync(0xffffffffu, c1, 4);
            float p2 = __shfl_xor_sync(0xffffffffu, c2, 4);
            float p3 = __shfl_xor_sync(0xffffffffu, c3, 4);
            unsigned h0, l0, h1, l1;
            int k2;
            if (!(grp & 1)) {
                split_pack(c0, p0, h0, l0);
                split_pack(c1, p1, h1, l1);
                k2 = (rowbase + grp) >> 1;
            } else {
                split_pack(p2, c2, h0, l0);
                split_pack(p3, c3, h1, l1);
                k2 = (rowbase + 7 + grp) >> 1;
            }
            int col0 = blockIdx.x*256 + wn + nt*8 + tig*2;
            if (col0 < LCOLS) {
                *(uint2*)&Cgh[(size_t)k2*LCOLS + col0] = make_uint2(h0, h1);
                *(uint2*)&Cgl[(size_t)k2*LCOLS + col0] = make_uint2(l0, l1);
            }
        }
    }
}

// ---------------- fused per-node weight banks (gate z=0, update z=1) ----------------
__global__ __launch_bounds__(256) void wgen_both(const float* __restrict__ gW,
                                                 const float* __restrict__ uW, int t)
{
    __shared__ float ne8[8][16];
    int tid = threadIdx.x;
    int n0 = blockIdx.x*8;
    int r2base = blockIdx.y*26;            // K2T = 104 = 4*26
    int isUpd = blockIdx.z;
    const float* neb = isUpd ? d_ne_u : d_ne_g;
    if (tid < 128) {
        int n = tid >> 4, d = tid & 15;
        ne8[n][d] = neb[(size_t)(t*NN + n0 + n)*DD + d];
    }
    __syncthreads();
    if (!isUpd) {
        int o = tid & 127, half = tid >> 7;
        for (int r2 = r2base + half; r2 < r2base + 26; r2 += 2) {
            int kg0 = 2*r2, kg1 = kg0 + 1;
            float g0[DD], g1[DD];
            if (kg0 < 195) {
                int s = kg0/65, i = kg0 - s*65;
                const float* gp = gW + (size_t)(s*CC + i)*OG + o;
#pragma unroll
                for (int d = 0; d < DD; d++) g0[d] = gp[(size_t)d*(3*CC*OG)];
            } else {
#pragma unroll
                for (int d = 0; d < DD; d++) g0[d] = 0.f;
            }
            if (kg1 < 195) {
                int s = kg1/65, i = kg1 - s*65;
                const float* gp = gW + (size_t)(s*CC + i)*OG + o;
#pragma unroll
                for (int d = 0; d < DD; d++) g1[d] = gp[(size_t)d*(3*CC*OG)];
            } else {
#pragma unroll
                for (int d = 0; d < DD; d++) g1[d] = 0.f;
            }
#pragma unroll
            for (int n = 0; n < 8; n++) {
                float w0 = 0.f, w1 = 0.f;
#pragma unroll
                for (int d = 0; d < DD; d++) {
                    float nv = ne8[n][d];
                    w0 += nv*g0[d]; w1 += nv*g1[d];
                }
                unsigned h, l;
                split_pack(w0, w1, h, l);
                size_t a = ((size_t)(n0+n)*K2T + r2)*OG + o;
                d_Wg[a] = h;
                d_Wg[WGSZ + a] = l;
            }
        }
    } else {
        int o = tid & 63, q = tid >> 6;
        for (int r2 = r2base + q; r2 < r2base + 26; r2 += 4) {
            int kg0 = 2*r2, kg1 = kg0 + 1;
            float g0[DD], g1[DD];
            if (kg0 < 195) {
                int s = kg0/65, i = kg0 - s*65;
                const float* gp = uW + (size_t)(s*CC + i)*OU + o;
#pragma unroll
                for (int d = 0; d < DD; d++) g0[d] = gp[(size_t)d*(3*CC*OU)];
            } else {
#pragma unroll
                for (int d = 0; d < DD; d++) g0[d] = 0.f;
            }
            if (kg1 < 195) {
                int s = kg1/65, i = kg1 - s*65;
                const float* gp = uW + (size_t)(s*CC + i)*OU + o;
#pragma unroll
                for (int d = 0; d < DD; d++) g1[d] = gp[(size_t)d*(3*CC*OU)];
            } else {
#pragma unroll
                for (int d = 0; d < DD; d++) g1[d] = 0.f;
            }
#pragma unroll
            for (int n = 0; n < 8; n++) {
                float w0 = 0.f, w1 = 0.f;
#pragma unroll
                for (int d = 0; d < DD; d++) {
                    float nv = ne8[n][d];
                    w0 += nv*g0[d]; w1 += nv*g1[d];
                }
                unsigned h, l;
                split_pack(w0, w1, h, l);
                size_t a = ((size_t)(n0+n)*K2T + r2)*OU + o;
                d_Wu[a] = h;
                d_Wu[WUSZ + a] = l;
            }
        }
    }
}

// ============ GCN epilogues: 2 nodes x 32 batches / block, 256 threads ============
// xraw stored as bf16 hi/lo ushort planes [2nd][32][STR]
#define XQ (2*32*STR)                                     // ushorts per plane
#define GATE_SMEM (2*XQ*2 + 2*8*136*4*2 + 2*128*4 + 2*16*4)   // 72832
#define UPD_SMEM  (2*XQ*2 + 2*8*72*4*2  + 2*64*4  + 2*16*4)   // 64128

__global__ __launch_bounds__(256, 3) void gate_epi_mma(
    const float* __restrict__ gb, const float* __restrict__ x, int t)
{
    extern __shared__ char smem[];
    unsigned short* xhp = (unsigned short*)smem;              // [2nd][32][STR]
    unsigned short* xlp = xhp + XQ;
    unsigned* WhB = (unsigned*)(xlp + XQ);                    // [2nd][8][136]
    unsigned* WlB = WhB + 2*8*136;
    float* sbias  = (float*)(WlB + 2*8*136);                  // [2][128]
    float* nes    = sbias + 2*128;                            // [2][16]

    int tid = threadIdx.x;
    int ip = blockIdx.x;
    int bh = blockIdx.y;
    int n0 = ip*2;
    int bbase = bh*32;

    const unsigned* Xh  = (const unsigned*)d_Xg;  const unsigned* Xl  = Xh  + (size_t)NP2*LCOLS;
    const unsigned* Y1h = (const unsigned*)d_Y1g; const unsigned* Y1l = Y1h + (size_t)NP2*LCOLS;
    const unsigned* Y2h = (const unsigned*)d_Y2g; const unsigned* Y2l = Y2h + (size_t)NP2*LCOLS;

    for (int e = tid; e < 32*CC; e += 256) {
        int bl = e / CC, i = e - (e/CC)*CC;
        size_t off = (size_t)ip*LCOLS + (bbase + bl)*CC + i;
        float x0, x1, y10, y11, y20, y21;
        unpack2(Xh[off],  Xl[off],  x0,  x1);
        unpack2(Y1h[off], Y1l[off], y10, y11);
        unpack2(Y2h[off], Y2l[off], y20, y21);
        int base0 = bl*STR + i;
        sp_store(xhp, xlp, base0,       x0);
        sp_store(xhp, xlp, base0 + 65,  y10);
        sp_store(xhp, xlp, base0 + 130, 2.f*y20 - x0);
        int base1 = 32*STR + base0;
        sp_store(xhp, xlp, base1,       x1);
        sp_store(xhp, xlp, base1 + 65,  y11);
        sp_store(xhp, xlp, base1 + 130, 2.f*y21 - x1);
    }
    for (int idx = tid; idx < 2*32*17; idx += 256) {
        int nd = idx / 544;
        int r = idx - nd*544;
        int bl = r / 17, k = r - bl*17;
        int pos = nd*32*STR + bl*STR + 195 + k;
        xhp[pos] = 0; xlp[pos] = 0;
    }
    if (tid < 32) {
        int nd = tid >> 4, d = tid & 15;
        nes[nd*16 + d] = d_ne_g[(size_t)(t*NN + n0 + nd)*DD + d];
    }
    __syncthreads();
    {
        int nd = tid >> 7, o = tid & 127;
        float s = 0.f;
#pragma unroll
        for (int d = 0; d < DD; d++) s += nes[nd*16 + d]*gb[d*OG + o];
        sbias[nd*128 + o] = s;
    }

    int wid = tid >> 5, lane = tid & 31;
    int nd = wid >> 2, w4 = wid & 3;
    int wn = w4*32;
    int grp = lane >> 2, tig = lane & 3;
    const unsigned short* xh = xhp + nd*32*STR;
    const unsigned short* xl = xlp + nd*32*STR;
    const unsigned* Wh = WhB + nd*1088;
    const unsigned* Wl = WlB + nd*1088;

    float acc[2][4][4];
#pragma unroll
    for (int i = 0; i < 2; i++)
#pragma unroll
        for (int j = 0; j < 4; j++)
#pragma unroll
            for (int c = 0; c < 4; c++) acc[i][j][c] = 0.f;

    for (int ch = 0; ch < 13; ch++) {
#pragma unroll
        for (int rep = 0; rep < 2; rep++) {
            int slot = tid + rep*256;
            int snd = slot >> 8, sr2 = (slot >> 5) & 7, so4 = (slot & 31) << 2;
            size_t a = ((size_t)(n0 + snd)*K2T + ch*8 + sr2)*OG + so4;
            *(uint4*)&WhB[snd*1088 + sr2*136 + so4] = *(const uint4*)&d_Wg[a];
            *(uint4*)&WlB[snd*1088 + sr2*136 + so4] = *(const uint4*)&d_Wg[WGSZ + a];
        }
        __syncthreads();

        unsigned bhf[4][2], blf[4][2];
#pragma unroll
        for (int nt = 0; nt < 4; nt++) {
            int o = wn + nt*8 + grp;
            bhf[nt][0] = Wh[tig*136 + o];     bhf[nt][1] = Wh[(tig+4)*136 + o];
            blf[nt][0] = Wl[tig*136 + o];     blf[nt][1] = Wl[(tig+4)*136 + o];
        }
        int kgA = ch*16 + 2*tig;
#pragma unroll
        for (int mt = 0; mt < 2; mt++) {
            int b0 = mt*16 + grp, b1 = b0 + 8;
            unsigned ah0 = *(const unsigned*)&xh[b0*STR + kgA];
            unsigned al0 = *(const unsigned*)&xl[b0*STR + kgA];
            unsigned ah1 = *(const unsigned*)&xh[b1*STR + kgA];
            unsigned al1 = *(const unsigned*)&xl[b1*STR + kgA];
            unsigned ah2 = *(const unsigned*)&xh[b0*STR + kgA + 8];
            unsigned al2 = *(const unsigned*)&xl[b0*STR + kgA + 8];
            unsigned ah3 = *(const unsigned*)&xh[b1*STR + kgA + 8];
            unsigned al3 = *(const unsigned*)&xl[b1*STR + kgA + 8];
#pragma unroll
            for (int nt = 0; nt < 4; nt++) {
                mma_bf16(acc[mt][nt][0], acc[mt][nt][1], acc[mt][nt][2], acc[mt][nt][3],
                         ah0, ah1, ah2, ah3, bhf[nt][0], bhf[nt][1]);
                mma_bf16(acc[mt][nt][0], acc[mt][nt][1], acc[mt][nt][2], acc[mt][nt][3],
                         ah0, ah1, ah2, ah3, blf[nt][0], blf[nt][1]);
                mma_bf16(acc[mt][nt][0], acc[mt][nt][1], acc[mt][nt][2], acc[mt][nt][3],
                         al0, al1, al2, al3, bhf[nt][0], bhf[nt][1]);
            }
        }
        __syncthreads();
    }

    // finalize: sigmoid; z -> zh smem ; r -> d_r
    float* zh = (float*)smem;   // reuse: [2nd][32][64]
    int n = n0 + nd;
#pragma unroll
    for (int mt = 0; mt < 2; mt++) {
#pragma unroll
        for (int nt = 0; nt < 4; nt++) {
            int o0 = wn + nt*8 + tig*2;
#pragma unroll
            for (int c = 0; c < 4; c++) {
                int bl = mt*16 + grp + ((c >> 1) ? 8 : 0);
                int b = bbase + bl;
                int o = o0 + (c & 1);
                float v = 1.f/(1.f + __expf(-(acc[mt][nt][c] + sbias[nd*128 + o])));
                if (o < HH) {
                    float hv = d_h[(size_t)(n*BB + b)*HH + o];
                    zh[nd*2048 + bl*64 + o] = v*hv;
                } else {
                    d_r[(size_t)(n*BB + b)*HH + (o - HH)] = v;
                }
            }
        }
    }
    __syncthreads();

    unsigned* Xuh = (unsigned*)d_Xu;
    unsigned* Xul = Xuh + (size_t)NP2*LCOLS;
    for (int idx = tid; idx < 2048; idx += 256) {
        int bl = idx >> 6, o = idx & 63;
        unsigned h, l;
        split_pack(zh[idx], zh[2048 + idx], h, l);
        Xuh[(size_t)ip*LCOLS + (bbase + bl)*CC + 1 + o] = h;
        Xul[(size_t)ip*LCOLS + (bbase + bl)*CC + 1 + o] = l;
    }
    if (tid < 32) {
        int b = bbase + tid;
        unsigned h, l;
        split_pack(x[(size_t)(b*TT + t)*NN + n0], x[(size_t)(b*TT + t)*NN + n0 + 1], h, l);
        Xuh[(size_t)ip*LCOLS + b*CC] = h;
        Xul[(size_t)ip*LCOLS + b*CC] = l;
    }
}

__global__ __launch_bounds__(256, 3) void update_epi_mma(
    const float* __restrict__ ub,
    float* __restrict__ out, const float* __restrict__ x, int t)
{
    extern __shared__ char smem[];
    unsigned short* xhp = (unsigned short*)smem;              // [2nd][32][STR]
    unsigned short* xlp = xhp + XQ;
    unsigned* WhB = (unsigned*)(xlp + XQ);                    // [2nd][8][72]
    unsigned* WlB = WhB + 2*8*72;
    float* sbias  = (float*)(WlB + 2*8*72);                   // [2][64]
    float* nes    = sbias + 2*64;                             // [2][16]

    int tid = threadIdx.x;
    int ip = blockIdx.x;
    int bh = blockIdx.y;
    int n0 = ip*2;
    int bbase = bh*32;

    const unsigned* Xh  = (const unsigned*)d_Xu;  const unsigned* Xl  = Xh  + (size_t)NP2*LCOLS;
    const unsigned* Y1h = (const unsigned*)d_Y1u; const unsigned* Y1l = Y1h + (size_t)NP2*LCOLS;
    const unsigned* Y2h = (const unsigned*)d_Y2u; const unsigned* Y2l = Y2h + (size_t)NP2*LCOLS;

    for (int e = tid; e < 32*CC; e += 256) {
        int bl = e / CC, i = e - (e/CC)*CC;
        size_t off = (size_t)ip*LCOLS + (bbase + bl)*CC + i;
        float x0, x1, y10, y11, y20, y21;
        unpack2(Xh[off],  Xl[off],  x0,  x1);
        unpack2(Y1h[off], Y1l[off], y10, y11);
        unpack2(Y2h[off], Y2l[off], y20, y21);
        int base0 = bl*STR + i;
        sp_store(xhp, xlp, base0,       x0);
        sp_store(xhp, xlp, base0 + 65,  y10);
        sp_store(xhp, xlp, base0 + 130, 2.f*y20 - x0);
        int base1 = 32*STR + base0;
        sp_store(xhp, xlp, base1,       x1);
        sp_store(xhp, xlp, base1 + 65,  y11);
        sp_store(xhp, xlp, base1 + 130, 2.f*y21 - x1);
    }
    for (int idx = tid; idx < 2*32*17; idx += 256) {
        int nd = idx / 544;
        int r = idx - nd*544;
        int bl = r / 17, k = r - bl*17;
        int pos = nd*32*STR + bl*STR + 195 + k;
        xhp[pos] = 0; xlp[pos] = 0;
    }
    if (tid < 32) {
        int nd = tid >> 4, d = tid & 15;
        nes[nd*16 + d] = d_ne_u[(size_t)(t*NN + n0 + nd)*DD + d];
    }
    __syncthreads();
    if (tid < 128) {
        int nd = tid >> 6, o = tid & 63;
        float s = 0.f;
#pragma unroll
        for (int d = 0; d < DD; d++) s += nes[nd*16 + d]*ub[d*OU + o];
        sbias[nd*64 + o] = s;
    }

    int wid = tid >> 5, lane = tid & 31;
    int nd = wid >> 2, w4 = wid & 3;
    int wn = w4*16;
    int grp = lane >> 2, tig = lane & 3;
    const unsigned short* xh = xhp + nd*32*STR;
    const unsigned short* xl = xlp + nd*32*STR;
    const unsigned* Wh = WhB + nd*576;
    const unsigned* Wl = WlB + nd*576;

    float acc[2][2][4];
#pragma unroll
    for (int i = 0; i < 2; i++)
#pragma unroll
        for (int j = 0; j < 2; j++)
#pragma unroll
            for (int c = 0; c < 4; c++) acc[i][j][c] = 0.f;

    for (int ch = 0; ch < 13; ch++) {
        {
            int snd = tid >> 7, sr2 = (tid >> 4) & 7, so4 = (tid & 15) << 2;
            size_t a = ((size_t)(n0 + snd)*K2T + ch*8 + sr2)*OU + so4;
            *(uint4*)&WhB[snd*576 + sr2*72 + so4] = *(const uint4*)&d_Wu[a];
            *(uint4*)&WlB[snd*576 + sr2*72 + so4] = *(const uint4*)&d_Wu[WUSZ + a];
        }
        __syncthreads();

        unsigned bhf[2][2], blf[2][2];
#pragma unroll
        for (int nt = 0; nt < 2; nt++) {
            int o = wn + nt*8 + grp;
            bhf[nt][0] = Wh[tig*72 + o];     bhf[nt][1] = Wh[(tig+4)*72 + o];
            blf[nt][0] = Wl[tig*72 + o];     blf[nt][1] = Wl[(tig+4)*72 + o];
        }
        int kgA = ch*16 + 2*tig;
#pragma unroll
        for (int mt = 0; mt < 2; mt++) {
            int b0 = mt*16 + grp, b1 = b0 + 8;
            unsigned ah0 = *(const unsigned*)&xh[b0*STR + kgA];
            unsigned al0 = *(const unsigned*)&xl[b0*STR + kgA];
            unsigned ah1 = *(const unsigned*)&xh[b1*STR + kgA];
            unsigned al1 = *(const unsigned*)&xl[b1*STR + kgA];
            unsigned ah2 = *(const unsigned*)&xh[b0*STR + kgA + 8];
            unsigned al2 = *(const unsigned*)&xl[b0*STR + kgA + 8];
            unsigned ah3 = *(const unsigned*)&xh[b1*STR + kgA + 8];
            unsigned al3 = *(const unsigned*)&xl[b1*STR + kgA + 8];
#pragma unroll
            for (int nt = 0; nt < 2; nt++) {
                mma_bf16(acc[mt][nt][0], acc[mt][nt][1], acc[mt][nt][2], acc[mt][nt][3],
                         ah0, ah1, ah2, ah3, bhf[nt][0], bhf[nt][1]);
                mma_bf16(acc[mt][nt][0], acc[mt][nt][1], acc[mt][nt][2], acc[mt][nt][3],
                         ah0, ah1, ah2, ah3, blf[nt][0], blf[nt][1]);
                mma_bf16(acc[mt][nt][0], acc[mt][nt][1], acc[mt][nt][2], acc[mt][nt][3],
                         al0, al1, al2, al3, bhf[nt][0], bhf[nt][1]);
            }
        }
        __syncthreads();
    }

    float* zh = (float*)smem;   // reuse: [2nd][32][64]
    int n = n0 + nd;
#pragma unroll
    for (int mt = 0; mt < 2; mt++) {
#pragma unroll
        for (int nt = 0; nt < 2; nt++) {
            int o0 = wn + nt*8 + tig*2;
#pragma unroll
            for (int c = 0; c < 4; c++) {
                int bl = mt*16 + grp + ((c >> 1) ? 8 : 0);
                int b = bbase + bl;
                int o = o0 + (c & 1);
                float hc = tanhf(acc[mt][nt][c] + sbias[nd*64 + o]);
                size_t idx = (size_t)(n*BB + b)*HH + o;
                float hv = d_h[idx];
                float rv = d_r[idx];
                float hn = rv*hv + (1.f - rv)*hc;
                d_h[idx] = hn;
                out[((size_t)(b*TT + t)*NN + n)*HH + o] = hn;
                zh[nd*2048 + bl*64 + o] = hn;
            }
        }
    }
    __syncthreads();

    if (t + 1 < TT) {
        unsigned* Xgh = (unsigned*)d_Xg;
        unsigned* Xgl = Xgh + (size_t)NP2*LCOLS;
        for (int idx = tid; idx < 2048; idx += 256) {
            int bl = idx >> 6, o = idx & 63;
            unsigned h, l;
            split_pack(zh[idx], zh[2048 + idx], h, l);
            Xgh[(size_t)ip*LCOLS + (bbase + bl)*CC + 1 + o] = h;
            Xgl[(size_t)ip*LCOLS + (bbase + bl)*CC + 1 + o] = l;
        }
        if (tid < 32) {
            int b = bbase + tid;
            unsigned h, l;
            split_pack(x[(size_t)(b*TT + t+1)*NN + n0], x[(size_t)(b*TT + t+1)*NN + n0 + 1], h, l);
            Xgh[(size_t)ip*LCOLS + b*CC] = h;
            Xgl[(size_t)ip*LCOLS + b*CC] = l;
        }
    }
}

// ---------------- host launcher ----------------
extern "C" void kernel_launch(void* const* d_in, const int* in_sizes, int n_in,
                              void* d_out, int out_size)
{
    const float *x = nullptr, *nodeE = nullptr, *timeE = nullptr;
    const float *gW = nullptr, *gb = nullptr, *uW = nullptr, *ub = nullptr;
    const float *ln16[4] = {nullptr, nullptr, nullptr, nullptr};
    int nln = 0;
    for (int i = 0; i < n_in; i++) {
        const float* p = (const float*)d_in[i];
        switch (in_sizes[i]) {
            case 786432: x = p; break;
            case 16384:  nodeE = p; break;
            case 192:    timeE = p; break;
            case 399360: gW = p; break;
            case 2048:   gb = p; break;
            case 199680: uW = p; break;
            case 1024:   ub = p; break;
            case 16:     if (nln < 4) ln16[nln++] = p; break;
            default: break;
        }
    }
    const float* glg = ln16[0]; const float* glb = ln16[1];
    const float* ulg = ln16[2]; const float* ulb = ln16[3];
    float* out = (float*)d_out;

    cudaFuncSetAttribute(mma_gemm2,      cudaFuncAttributeMaxDynamicSharedMemorySize, GEMM_SMEM);
    cudaFuncSetAttribute(gate_epi_mma,   cudaFuncAttributeMaxDynamicSharedMemorySize, GATE_SMEM);
    cudaFuncSetAttribute(update_epi_mma, cudaFuncAttributeMaxDynamicSharedMemorySize, UPD_SMEM);

    dim3 egrid(NP2, 2);          // node pairs x batch halves
    dim3 wgrid(NN/8, 4, 2);      // node groups x r2 quarters x {gate,update}
    dim3 ggrid((LCOLS + 255)/256, NN/128);   // (17, 8) = 136 blocks

    // launch order: slot 4 = mma_gemm2 (ncu capture target)
    zero_pack0_kernel<<<(NN*BB*HH + 255)/256, 256>>>(x);                              // 1
    score_fused_kernel<<<dim3(8, 8, 2*TT), 256>>>(nodeE, timeE, glg, glb, ulg, ulb);  // 2
    softmax_kernel<<<dim3(128, TT, 2), 256>>>();                                       // 3

    for (int t = 0; t < TT; t++) {
        mma_gemm2<<<ggrid, 256, GEMM_SMEM>>>(0, t, 0, 1);   // Y1g = Sg @ Xg   (4 at t=0)
        if (t == 0)
            compute_ne_kernel<<<(TT*NN + 255)/256, 256>>>(nodeE, timeE, glg, glb, ulg, ulb);
        wgen_both<<<wgrid, 256>>>(gW, uW, t);
        mma_gemm2<<<ggrid, 256, GEMM_SMEM>>>(0, t, 1, 2);   // Y2g = Sg @ Y1g
        gate_epi_mma<<<egrid, 256, GATE_SMEM>>>(gb, x, t);
        mma_gemm2<<<ggrid, 256, GEMM_SMEM>>>(1, t, 3, 4);   // Y1u = Su @ Xu
        mma_gemm2<<<ggrid, 256, GEMM_SMEM>>>(1, t, 4, 5);   // Y2u = Su @ Y1u
        update_epi_mma<<<egrid, 256, UPD_SMEM>>>(ub, out, x, t);
    }
}

// round 17
// speedup vs baseline: 1.3242x; 1.0090x over previous
#include <cuda_runtime.h>
#include <cuda_bf16.h>
#include <math.h>

// Problem constants
#define NN 1024
#define BB 64
#define TT 12
#define DD 16
#define HH 64
#define CC 65
#define LCOLS (BB*CC)   // 4160
#define OG 128
#define OU 64
#define NP2 512         // node pairs
#define K2T 104         // epilogue K pairs
#define STR 212         // epilogue ushort row stride

// ---------------- scratch ----------------
__device__ float d_ne_g[TT*NN*DD];
__device__ float d_ne_u[TT*NN*DD];
__device__ float d_Sg[(size_t)TT*NN*NN];
__device__ float d_Su[(size_t)TT*NN*NN];
__device__ float d_h [NN*BB*HH];
__device__ float d_r [NN*BB*HH];
// PACKED bf16 hi/lo planes: [0,512*LCOLS) hi uints [npair][col], lo after
__device__ float d_Xg [(size_t)NN*LCOLS];
__device__ float d_Y1g[(size_t)NN*LCOLS];
__device__ float d_Y2g[(size_t)NN*LCOLS];
__device__ float d_Xu [(size_t)NN*LCOLS];
__device__ float d_Y1u[(size_t)NN*LCOLS];
__device__ float d_Y2u[(size_t)NN*LCOLS];
// weight banks, parity double-buffered: [parity][hi/lo][...]
#define WGSZ ((size_t)NN*K2T*OG)
#define WUSZ ((size_t)NN*K2T*OU)
__device__ unsigned d_Wg[4*WGSZ];
__device__ unsigned d_Wu[4*WUSZ];

// ---------------- helpers ----------------
__device__ __forceinline__ unsigned pack_bf16(float v0, float v1)
{
    __nv_bfloat162 t = __floats2bfloat162_rn(v0, v1);
    return *(unsigned*)&t;
}
__device__ __forceinline__ void split_pack(float v0, float v1, unsigned& hi, unsigned& lo)
{
    __nv_bfloat16 h0 = __float2bfloat16(v0);
    __nv_bfloat16 h1 = __float2bfloat16(v1);
    float r0 = v0 - __bfloat162float(h0);
    float r1 = v1 - __bfloat162float(h1);
    hi = ((unsigned)__bfloat16_as_ushort(h1) << 16) | (unsigned)__bfloat16_as_ushort(h0);
    lo = pack_bf16(r0, r1);
}
__device__ __forceinline__ void unpack2(unsigned h, unsigned l, float& a, float& b)
{
    __nv_bfloat162 hh = *reinterpret_cast<__nv_bfloat162*>(&h);
    __nv_bfloat162 ll = *reinterpret_cast<__nv_bfloat162*>(&l);
    a = __bfloat162float(hh.x) + __bfloat162float(ll.x);
    b = __bfloat162float(hh.y) + __bfloat162float(ll.y);
}
__device__ __forceinline__ void sp_store(unsigned short* xh, unsigned short* xl, int idx, float v)
{
    __nv_bfloat16 h = __float2bfloat16(v);
    float r = v - __bfloat162float(h);
    xh[idx] = __bfloat16_as_ushort(h);
    xl[idx] = __bfloat16_as_ushort(__float2bfloat16(r));
}
__device__ __forceinline__ void mma_bf16(float& c0, float& c1, float& c2, float& c3,
    unsigned a0, unsigned a1, unsigned a2, unsigned a3, unsigned b0, unsigned b1)
{
    asm volatile("mma.sync.aligned.m16n8k16.row.col.f32.bf16.bf16.f32 "
        "{%0,%1,%2,%3}, {%4,%5,%6,%7}, {%8,%9}, {%0,%1,%2,%3};\n"
        : "+f"(c0), "+f"(c1), "+f"(c2), "+f"(c3)
        : "r"(a0), "r"(a1), "r"(a2), "r"(a3), "r"(b0), "r"(b1));
}

// ---------------- fused zero_h + pack Xg(t=0) ----------------
__global__ void zero_pack0_kernel(const float* __restrict__ x)
{
    int idx = blockIdx.x*blockDim.x + threadIdx.x;
    if (idx < NN*BB*HH) d_h[idx] = 0.f;
    if (idx < NP2*LCOLS) {
        int i = idx / LCOLS;
        int c = idx - i*LCOLS;
        int b = c / CC, cc = c - b*CC;
        unsigned h = 0, l = 0;
        if (cc == 0)
            split_pack(x[(size_t)(b*TT)*NN + 2*i], x[(size_t)(b*TT)*NN + 2*i + 1], h, l);
        unsigned* Xh = (unsigned*)d_Xg;
        Xh[idx] = h;
        Xh[(size_t)NP2*LCOLS + idx] = l;
    }
}

// ---------------- layernormed embeddings, all t ----------------
__global__ void compute_ne_kernel(const float* __restrict__ nodeE,
                                  const float* __restrict__ timeE,
                                  const float* __restrict__ gg, const float* __restrict__ gbeta,
                                  const float* __restrict__ ug, const float* __restrict__ ubeta)
{
    int idx = blockIdx.x*blockDim.x + threadIdx.x;
    if (idx >= TT*NN) return;
    int t = idx >> 10;
    int n = idx & (NN-1);
    float v[DD];
    float mu = 0.f;
#pragma unroll
    for (int d = 0; d < DD; d++) { v[d] = nodeE[n*DD+d] + timeE[t*DD+d]; mu += v[d]; }
    mu *= (1.f/DD);
    float var = 0.f;
#pragma unroll
    for (int d = 0; d < DD; d++) { float dv = v[d]-mu; var += dv*dv; }
    var *= (1.f/DD);
    float inv = 1.f / sqrtf(var + 1e-12f);
#pragma unroll
    for (int d = 0; d < DD; d++) {
        float nv = (v[d]-mu)*inv;
        d_ne_g[idx*DD+d] = nv*gg[d] + gbeta[d];
        d_ne_u[idx*DD+d] = nv*ug[d] + ubeta[d];
    }
}

// ---------------- scores with inline LN: G = ne @ ne^T ----------------
__global__ __launch_bounds__(256) void score_fused_kernel(
    const float* __restrict__ nodeE, const float* __restrict__ timeE,
    const float* __restrict__ gg, const float* __restrict__ gbeta,
    const float* __restrict__ ug, const float* __restrict__ ubeta)
{
    int z = blockIdx.z;
    int which = (z >= TT) ? 1 : 0;
    int t = which ? (z - TT) : z;
    float* __restrict__ G = (which ? d_Su : d_Sg) + (size_t)t*NN*NN;
    const float* lg = which ? ug : gg;
    const float* lb = which ? ubeta : gbeta;
    __shared__ float Rt[DD][132];
    __shared__ float Ct[DD][132];
    int tid = threadIdx.x;
    {
        int isCol = tid >> 7, r = tid & 127;
        int n = (isCol ? blockIdx.x : blockIdx.y)*128 + r;
        float v[DD];
        float mu = 0.f;
#pragma unroll
        for (int d = 0; d < DD; d++) { v[d] = nodeE[n*DD+d] + timeE[t*DD+d]; mu += v[d]; }
        mu *= (1.f/DD);
        float var = 0.f;
#pragma unroll
        for (int d = 0; d < DD; d++) { float dv = v[d]-mu; var += dv*dv; }
        var *= (1.f/DD);
        float inv = 1.f / sqrtf(var + 1e-12f);
#pragma unroll
        for (int d = 0; d < DD; d++) {
            float nv = (v[d]-mu)*inv*lg[d] + lb[d];
            if (isCol) Ct[d][r] = nv; else Rt[d][r] = nv;
        }
    }
    __syncthreads();
    int ty = tid >> 4, tx = tid & 15;
    int r0 = ty*8, c0 = tx*8;
    float acc[8][8];
#pragma unroll
    for (int i = 0; i < 8; i++)
#pragma unroll
        for (int j = 0; j < 8; j++) acc[i][j] = 0.f;
#pragma unroll
    for (int k = 0; k < DD; k++) {
        float rv[8], cv[8];
        *(float4*)&rv[0] = *(const float4*)&Rt[k][r0];
        *(float4*)&rv[4] = *(const float4*)&Rt[k][r0+4];
        *(float4*)&cv[0] = *(const float4*)&Ct[k][c0];
        *(float4*)&cv[4] = *(const float4*)&Ct[k][c0+4];
#pragma unroll
        for (int i = 0; i < 8; i++)
#pragma unroll
            for (int j = 0; j < 8; j++) acc[i][j] += rv[i]*cv[j];
    }
#pragma unroll
    for (int i = 0; i < 8; i++) {
        float* gp = G + (size_t)(blockIdx.y*128 + r0 + i)*NN + blockIdx.x*128 + c0;
        *(float4*)gp     = make_float4(acc[i][0], acc[i][1], acc[i][2], acc[i][3]);
        *(float4*)(gp+4) = make_float4(acc[i][4], acc[i][5], acc[i][6], acc[i][7]);
    }
}

// ---------------- row softmax, output packed bf16 hi/lo (in-place) ----------------
__global__ __launch_bounds__(256) void softmax_kernel()
{
    int which = blockIdx.z, t = blockIdx.y;
    float* S = (which ? d_Su : d_Sg) + (size_t)t*NN*NN;
    int warp = threadIdx.x >> 5, lane = threadIdx.x & 31;
    int row = blockIdx.x*8 + warp;
    float4* p = (float4*)(S + (size_t)row*NN);
    float4 v[8];
    float mx = -1e30f;
#pragma unroll
    for (int i = 0; i < 8; i++) {
        v[i] = p[lane + i*32];
        mx = fmaxf(mx, fmaxf(fmaxf(v[i].x, v[i].y), fmaxf(v[i].z, v[i].w)));
    }
#pragma unroll
    for (int o = 16; o > 0; o >>= 1) mx = fmaxf(mx, __shfl_xor_sync(0xffffffffu, mx, o));
    float sum = 0.f;
#pragma unroll
    for (int i = 0; i < 8; i++) {
        v[i].x = __expf(v[i].x - mx); v[i].y = __expf(v[i].y - mx);
        v[i].z = __expf(v[i].z - mx); v[i].w = __expf(v[i].w - mx);
        sum += v[i].x + v[i].y + v[i].z + v[i].w;
    }
#pragma unroll
    for (int o = 16; o > 0; o >>= 1) sum += __shfl_xor_sync(0xffffffffu, sum, o);
    float inv = 1.f / sum;
    unsigned* ur = (unsigned*)(S + (size_t)row*NN);
#pragma unroll
    for (int i = 0; i < 8; i++) {
        float a = v[i].x*inv, b = v[i].y*inv, c = v[i].z*inv, d = v[i].w*inv;
        unsigned h0, l0, h1, l1;
        split_pack(a, b, h0, l0);
        split_pack(c, d, h1, l1);
        int j0 = 2*(lane + i*32);
        ur[j0]       = h0; ur[j0+1]       = h1;
        ur[512 + j0] = l0; ur[512 + j0+1] = l1;
    }
}

// ---------------- bf16x3 GEMM: C = S @ B (packed hi/lo), R13 config ----------------
__device__ __forceinline__ const float* gemm_src(int id)
{
    switch (id) {
        case 0: return d_Xg;  case 1: return d_Y1g; case 2: return d_Y2g;
        case 3: return d_Xu;  case 4: return d_Y1u; default: return d_Y2u;
    }
}
__device__ __forceinline__ float* gemm_dst(int id)
{
    switch (id) {
        case 1: return d_Y1g; case 2: return d_Y2g;
        case 4: return d_Y1u; default: return d_Y2u;
    }
}

#define APAD 136
#define BPAD 264
#define GEMM_SMEM ((2*8*APAD*2 + 2*8*BPAD*2)*4)   // 51200 bytes

__global__ __launch_bounds__(256) void mma_gemm2(int su, int t, int bsel, int csel)
{
    extern __shared__ unsigned sm[];
    unsigned* AhS = sm;
    unsigned* AlS = AhS + 2*8*APAD;
    unsigned* BhS = AlS + 2*8*APAD;
    unsigned* BlS = BhS + 2*8*BPAD;

    const unsigned* Apk = (const unsigned*)((su ? d_Su : d_Sg) + (size_t)t*NN*NN);
    const unsigned* Bgh = (const unsigned*)gemm_src(bsel);
    const unsigned* Bgl = Bgh + (size_t)NP2*LCOLS;
    unsigned* Cgh = (unsigned*)gemm_dst(csel);
    unsigned* Cgl = Cgh + (size_t)NP2*LCOLS;

    int tid = threadIdx.x, warp = tid >> 5, lane = tid & 31;
    int wm = (warp >> 2)*64, wn = (warp & 3)*64;
    int grp = lane >> 2, tig = lane & 3;

    int aRow = tid & 127, aHalf = tid >> 7;
    const unsigned* ApH = Apk + (size_t)(blockIdx.y*128 + aRow)*1024 + aHalf*4;

    int bK2 = tid >> 5, bC4 = tid & 31;
    int colr0 = blockIdx.x*256 + bC4*4;
    int colr1 = colr0 + 128;
    bool ok0 = colr0 < LCOLS, ok1 = colr1 < LCOLS;

    float acc[4][8][4];
#pragma unroll
    for (int i = 0; i < 4; i++)
#pragma unroll
        for (int j = 0; j < 8; j++)
#pragma unroll
            for (int c = 0; c < 4; c++) acc[i][j][c] = 0.f;

    const uint4 z4 = make_uint4(0,0,0,0);
    {
        uint4 h = *(const uint4*)ApH;
        uint4 l = *(const uint4*)(ApH + 512);
        int ab = aHalf*4*APAD;
        AhS[ab + 0*APAD + aRow] = h.x; AhS[ab + 1*APAD + aRow] = h.y;
        AhS[ab + 2*APAD + aRow] = h.z; AhS[ab + 3*APAD + aRow] = h.w;
        AlS[ab + 0*APAD + aRow] = l.x; AlS[ab + 1*APAD + aRow] = l.y;
        AlS[ab + 2*APAD + aRow] = l.z; AlS[ab + 3*APAD + aRow] = l.w;
        size_t brow = (size_t)bK2*LCOLS;
        uint4 b0h = ok0 ? *(const uint4*)(Bgh + brow + colr0) : z4;
        uint4 b1h = ok1 ? *(const uint4*)(Bgh + brow + colr1) : z4;
        uint4 b0l = ok0 ? *(const uint4*)(Bgl + brow + colr0) : z4;
        uint4 b1l = ok1 ? *(const uint4*)(Bgl + brow + colr1) : z4;
        int bb = bK2*BPAD;
        *(uint4*)&BhS[bb + bC4*4]       = b0h;
        *(uint4*)&BhS[bb + 128 + bC4*4] = b1h;
        *(uint4*)&BlS[bb + bC4*4]       = b0l;
        *(uint4*)&BlS[bb + 128 + bC4*4] = b1l;
    }
    __syncthreads();

    int buf = 0;
    for (int k0 = 0; k0 < 1024; k0 += 16) {
        bool pf = (k0 + 16) < 1024;
        uint4 ph, pl, pb0h, pb1h, pb0l, pb1l;
        if (pf) {
            int k2g = (k0 + 16) >> 1;
            ph = *(const uint4*)(ApH + k2g);
            pl = *(const uint4*)(ApH + 512 + k2g);
            size_t brow = (size_t)(k2g + bK2)*LCOLS;
            pb0h = ok0 ? *(const uint4*)(Bgh + brow + colr0) : z4;
            pb1h = ok1 ? *(const uint4*)(Bgh + brow + colr1) : z4;
            pb0l = ok0 ? *(const uint4*)(Bgl + brow + colr0) : z4;
            pb1l = ok1 ? *(const uint4*)(Bgl + brow + colr1) : z4;
        }
        const unsigned* AhB = AhS + buf*8*APAD;
        const unsigned* AlB = AlS + buf*8*APAD;
        const unsigned* BhB = BhS + buf*8*BPAD;
        const unsigned* BlB = BlS + buf*8*BPAD;

        unsigned bh[8][2], bl[8][2];
#pragma unroll
        for (int nt = 0; nt < 8; nt++) {
            int o = wn + nt*8 + grp;
            bh[nt][0] = BhB[tig*BPAD + o];     bh[nt][1] = BhB[(tig+4)*BPAD + o];
            bl[nt][0] = BlB[tig*BPAD + o];     bl[nt][1] = BlB[(tig+4)*BPAD + o];
        }
#pragma unroll
        for (int mt = 0; mt < 4; mt++) {
            int m = wm + mt*16;
            unsigned ah0 = AhB[tig*APAD + m+grp];
            unsigned ah1 = AhB[tig*APAD + m+grp+8];
            unsigned ah2 = AhB[(tig+4)*APAD + m+grp];
            unsigned ah3 = AhB[(tig+4)*APAD + m+grp+8];
            unsigned al0 = AlB[tig*APAD + m+grp];
            unsigned al1 = AlB[tig*APAD + m+grp+8];
            unsigned al2 = AlB[(tig+4)*APAD + m+grp];
            unsigned al3 = AlB[(tig+4)*APAD + m+grp+8];
#pragma unroll
            for (int nt = 0; nt < 8; nt++) {
                mma_bf16(acc[mt][nt][0], acc[mt][nt][1], acc[mt][nt][2], acc[mt][nt][3],
                         ah0, ah1, ah2, ah3, bh[nt][0], bh[nt][1]);
                mma_bf16(acc[mt][nt][0], acc[mt][nt][1], acc[mt][nt][2], acc[mt][nt][3],
                         ah0, ah1, ah2, ah3, bl[nt][0], bl[nt][1]);
                mma_bf16(acc[mt][nt][0], acc[mt][nt][1], acc[mt][nt][2], acc[mt][nt][3],
                         al0, al1, al2, al3, bh[nt][0], bh[nt][1]);
            }
        }
        if (pf) {
            int nb = buf ^ 1;
            int ab = nb*8*APAD + aHalf*4*APAD;
            AhS[ab + 0*APAD + aRow] = ph.x; AhS[ab + 1*APAD + aRow] = ph.y;
            AhS[ab + 2*APAD + aRow] = ph.z; AhS[ab + 3*APAD + aRow] = ph.w;
            AlS[ab + 0*APAD + aRow] = pl.x; AlS[ab + 1*APAD + aRow] = pl.y;
            AlS[ab + 2*APAD + aRow] = pl.z; AlS[ab + 3*APAD + aRow] = pl.w;
            int bb = nb*8*BPAD + bK2*BPAD;
            *(uint4*)&BhS[bb + bC4*4]       = pb0h;
            *(uint4*)&BhS[bb + 128 + bC4*4] = pb1h;
            *(uint4*)&BlS[bb + bC4*4]       = pb0l;
            *(uint4*)&BlS[bb + 128 + bC4*4] = pb1l;
            __syncthreads();
            buf = nb;
        }
    }

#pragma unroll
    for (int mt = 0; mt < 4; mt++) {
        int rowbase = blockIdx.y*128 + wm + mt*16;
#pragma unroll
        for (int nt = 0; nt < 8; nt++) {
            float c0 = acc[mt][nt][0], c1 = acc[mt][nt][1];
            float c2 = acc[mt][nt][2], c3 = acc[mt][nt][3];
            float p0 = __shfl_xor_sync(0xffffffffu, c0, 4);
            float p1 = __shfl_xor_sync(0xffffffffu, c1, 4);
            float p2 = __shfl_xor_sync(0xffffffffu, c2, 4);
            float p3 = __shfl_xor_sync(0xffffffffu, c3, 4);
            unsigned h0, l0, h1, l1;
            int k2;
            if (!(grp & 1)) {
                split_pack(c0, p0, h0, l0);
                split_pack(c1, p1, h1, l1);
                k2 = (rowbase + grp) >> 1;
            } else {
                split_pack(p2, c2, h0, l0);
                split_pack(p3, c3, h1, l1);
                k2 = (rowbase + 7 + grp) >> 1;
            }
            int col0 = blockIdx.x*256 + wn + nt*8 + tig*2;
            if (col0 < LCOLS) {
                *(uint2*)&Cgh[(size_t)k2*LCOLS + col0] = make_uint2(h0, h1);
                *(uint2*)&Cgl[(size_t)k2*LCOLS + col0] = make_uint2(l0, l1);
            }
        }
    }
}

// ---------------- fused per-node weight banks (gate z=0, update z=1) ----------------
__global__ __launch_bounds__(256) void wgen_both(const float* __restrict__ gW,
                                                 const float* __restrict__ uW,
                                                 int t, int parity)
{
    __shared__ float ne8[8][16];
    int tid = threadIdx.x;
    int n0 = blockIdx.x*8;
    int r2base = blockIdx.y*26;
    int isUpd = blockIdx.z;
    const float* neb = isUpd ? d_ne_u : d_ne_g;
    if (tid < 128) {
        int n = tid >> 4, d = tid & 15;
        ne8[n][d] = neb[(size_t)(t*NN + n0 + n)*DD + d];
    }
    __syncthreads();
    if (!isUpd) {
        size_t pb = (size_t)parity*2*WGSZ;
        int o = tid & 127, half = tid >> 7;
        for (int r2 = r2base + half; r2 < r2base + 26; r2 += 2) {
            int kg0 = 2*r2, kg1 = kg0 + 1;
            float g0[DD], g1[DD];
            if (kg0 < 195) {
                int s = kg0/65, i = kg0 - s*65;
                const float* gp = gW + (size_t)(s*CC + i)*OG + o;
#pragma unroll
                for (int d = 0; d < DD; d++) g0[d] = gp[(size_t)d*(3*CC*OG)];
            } else {
#pragma unroll
                for (int d = 0; d < DD; d++) g0[d] = 0.f;
            }
            if (kg1 < 195) {
                int s = kg1/65, i = kg1 - s*65;
                const float* gp = gW + (size_t)(s*CC + i)*OG + o;
#pragma unroll
                for (int d = 0; d < DD; d++) g1[d] = gp[(size_t)d*(3*CC*OG)];
            } else {
#pragma unroll
                for (int d = 0; d < DD; d++) g1[d] = 0.f;
            }
#pragma unroll
            for (int n = 0; n < 8; n++) {
                float w0 = 0.f, w1 = 0.f;
#pragma unroll
                for (int d = 0; d < DD; d++) {
                    float nv = ne8[n][d];
                    w0 += nv*g0[d]; w1 += nv*g1[d];
                }
                unsigned h, l;
                split_pack(w0, w1, h, l);
                size_t a = pb + ((size_t)(n0+n)*K2T + r2)*OG + o;
                d_Wg[a] = h;
                d_Wg[WGSZ + a] = l;
            }
        }
    } else {
        size_t pb = (size_t)parity*2*WUSZ;
        int o = tid & 63, q = tid >> 6;
        for (int r2 = r2base + q; r2 < r2base + 26; r2 += 4) {
            int kg0 = 2*r2, kg1 = kg0 + 1;
            float g0[DD], g1[DD];
            if (kg0 < 195) {
                int s = kg0/65, i = kg0 - s*65;
                const float* gp = uW + (size_t)(s*CC + i)*OU + o;
#pragma unroll
                for (int d = 0; d < DD; d++) g0[d] = gp[(size_t)d*(3*CC*OU)];
            } else {
#pragma unroll
                for (int d = 0; d < DD; d++) g0[d] = 0.f;
            }
            if (kg1 < 195) {
                int s = kg1/65, i = kg1 - s*65;
                const float* gp = uW + (size_t)(s*CC + i)*OU + o;
#pragma unroll
                for (int d = 0; d < DD; d++) g1[d] = gp[(size_t)d*(3*CC*OU)];
            } else {
#pragma unroll
                for (int d = 0; d < DD; d++) g1[d] = 0.f;
            }
#pragma unroll
            for (int n = 0; n < 8; n++) {
                float w0 = 0.f, w1 = 0.f;
#pragma unroll
                for (int d = 0; d < DD; d++) {
                    float nv = ne8[n][d];
                    w0 += nv*g0[d]; w1 += nv*g1[d];
                }
                unsigned h, l;
                split_pack(w0, w1, h, l);
                size_t a = pb + ((size_t)(n0+n)*K2T + r2)*OU + o;
                d_Wu[a] = h;
                d_Wu[WUSZ + a] = l;
            }
        }
    }
}

// ============ GCN epilogues: 2 nodes x 32 batches / block, 256 threads ============
#define XQ (2*32*STR)
#define GATE_SMEM (2*XQ*2 + 2*8*136*4*2 + 2*128*4 + 2*16*4)   // 72832
#define UPD_SMEM  (2*XQ*2 + 2*8*72*4*2  + 2*64*4  + 2*16*4)   // 64128

__global__ __launch_bounds__(256, 3) void gate_epi_mma(
    const float* __restrict__ gb, const float* __restrict__ x, int t, int parity)
{
    extern __shared__ char smem[];
    unsigned short* xhp = (unsigned short*)smem;
    unsigned short* xlp = xhp + XQ;
    unsigned* WhB = (unsigned*)(xlp + XQ);
    unsigned* WlB = WhB + 2*8*136;
    float* sbias  = (float*)(WlB + 2*8*136);
    float* nes    = sbias + 2*128;

    int tid = threadIdx.x;
    int ip = blockIdx.x;
    int bh = blockIdx.y;
    int n0 = ip*2;
    int bbase = bh*32;
    size_t pb = (size_t)parity*2*WGSZ;

    const unsigned* Xh  = (const unsigned*)d_Xg;  const unsigned* Xl  = Xh  + (size_t)NP2*LCOLS;
    const unsigned* Y1h = (const unsigned*)d_Y1g; const unsigned* Y1l = Y1h + (size_t)NP2*LCOLS;
    const unsigned* Y2h = (const unsigned*)d_Y2g; const unsigned* Y2l = Y2h + (size_t)NP2*LCOLS;

    for (int e = tid; e < 32*CC; e += 256) {
        int bl = e / CC, i = e - (e/CC)*CC;
        size_t off = (size_t)ip*LCOLS + (bbase + bl)*CC + i;
        float x0, x1, y10, y11, y20, y21;
        unpack2(Xh[off],  Xl[off],  x0,  x1);
        unpack2(Y1h[off], Y1l[off], y10, y11);
        unpack2(Y2h[off], Y2l[off], y20, y21);
        int base0 = bl*STR + i;
        sp_store(xhp, xlp, base0,       x0);
        sp_store(xhp, xlp, base0 + 65,  y10);
        sp_store(xhp, xlp, base0 + 130, 2.f*y20 - x0);
        int base1 = 32*STR + base0;
        sp_store(xhp, xlp, base1,       x1);
        sp_store(xhp, xlp, base1 + 65,  y11);
        sp_store(xhp, xlp, base1 + 130, 2.f*y21 - x1);
    }
    for (int idx = tid; idx < 2*32*17; idx += 256) {
        int nd = idx / 544;
        int r = idx - nd*544;
        int bl = r / 17, k = r - bl*17;
        int pos = nd*32*STR + bl*STR + 195 + k;
        xhp[pos] = 0; xlp[pos] = 0;
    }
    if (tid < 32) {
        int nd = tid >> 4, d = tid & 15;
        nes[nd*16 + d] = d_ne_g[(size_t)(t*NN + n0 + nd)*DD + d];
    }
    __syncthreads();
    {
        int nd = tid >> 7, o = tid & 127;
        float s = 0.f;
#pragma unroll
        for (int d = 0; d < DD; d++) s += nes[nd*16 + d]*gb[d*OG + o];
        sbias[nd*128 + o] = s;
    }

    int wid = tid >> 5, lane = tid & 31;
    int nd = wid >> 2, w4 = wid & 3;
    int wn = w4*32;
    int grp = lane >> 2, tig = lane & 3;
    const unsigned short* xh = xhp + nd*32*STR;
    const unsigned short* xl = xlp + nd*32*STR;
    const unsigned* Wh = WhB + nd*1088;
    const unsigned* Wl = WlB + nd*1088;

    float acc[2][4][4];
#pragma unroll
    for (int i = 0; i < 2; i++)
#pragma unroll
        for (int j = 0; j < 4; j++)
#pragma unroll
            for (int c = 0; c < 4; c++) acc[i][j][c] = 0.f;

    for (int ch = 0; ch < 13; ch++) {
#pragma unroll
        for (int rep = 0; rep < 2; rep++) {
            int slot = tid + rep*256;
            int snd = slot >> 8, sr2 = (slot >> 5) & 7, so4 = (slot & 31) << 2;
            size_t a = pb + ((size_t)(n0 + snd)*K2T + ch*8 + sr2)*OG + so4;
            *(uint4*)&WhB[snd*1088 + sr2*136 + so4] = *(const uint4*)&d_Wg[a];
            *(uint4*)&WlB[snd*1088 + sr2*136 + so4] = *(const uint4*)&d_Wg[WGSZ + a];
        }
        __syncthreads();

        unsigned bhf[4][2], blf[4][2];
#pragma unroll
        for (int nt = 0; nt < 4; nt++) {
            int o = wn + nt*8 + grp;
            bhf[nt][0] = Wh[tig*136 + o];     bhf[nt][1] = Wh[(tig+4)*136 + o];
            blf[nt][0] = Wl[tig*136 + o];     blf[nt][1] = Wl[(tig+4)*136 + o];
        }
        int kgA = ch*16 + 2*tig;
#pragma unroll
        for (int mt = 0; mt < 2; mt++) {
            int b0 = mt*16 + grp, b1 = b0 + 8;
            unsigned ah0 = *(const unsigned*)&xh[b0*STR + kgA];
            unsigned al0 = *(const unsigned*)&xl[b0*STR + kgA];
            unsigned ah1 = *(const unsigned*)&xh[b1*STR + kgA];
            unsigned al1 = *(const unsigned*)&xl[b1*STR + kgA];
            unsigned ah2 = *(const unsigned*)&xh[b0*STR + kgA + 8];
            unsigned al2 = *(const unsigned*)&xl[b0*STR + kgA + 8];
            unsigned ah3 = *(const unsigned*)&xh[b1*STR + kgA + 8];
            unsigned al3 = *(const unsigned*)&xl[b1*STR + kgA + 8];
#pragma unroll
            for (int nt = 0; nt < 4; nt++) {
                mma_bf16(acc[mt][nt][0], acc[mt][nt][1], acc[mt][nt][2], acc[mt][nt][3],
                         ah0, ah1, ah2, ah3, bhf[nt][0], bhf[nt][1]);
                mma_bf16(acc[mt][nt][0], acc[mt][nt][1], acc[mt][nt][2], acc[mt][nt][3],
                         ah0, ah1, ah2, ah3, blf[nt][0], blf[nt][1]);
                mma_bf16(acc[mt][nt][0], acc[mt][nt][1], acc[mt][nt][2], acc[mt][nt][3],
                         al0, al1, al2, al3, bhf[nt][0], bhf[nt][1]);
            }
        }
        __syncthreads();
    }

    float* zh = (float*)smem;
    int n = n0 + nd;
#pragma unroll
    for (int mt = 0; mt < 2; mt++) {
#pragma unroll
        for (int nt = 0; nt < 4; nt++) {
            int o0 = wn + nt*8 + tig*2;
#pragma unroll
            for (int c = 0; c < 4; c++) {
                int bl = mt*16 + grp + ((c >> 1) ? 8 : 0);
                int b = bbase + bl;
                int o = o0 + (c & 1);
                float v = 1.f/(1.f + __expf(-(acc[mt][nt][c] + sbias[nd*128 + o])));
                if (o < HH) {
                    float hv = d_h[(size_t)(n*BB + b)*HH + o];
                    zh[nd*2048 + bl*64 + o] = v*hv;
                } else {
                    d_r[(size_t)(n*BB + b)*HH + (o - HH)] = v;
                }
            }
        }
    }
    __syncthreads();

    unsigned* Xuh = (unsigned*)d_Xu;
    unsigned* Xul = Xuh + (size_t)NP2*LCOLS;
    for (int idx = tid; idx < 2048; idx += 256) {
        int bl = idx >> 6, o = idx & 63;
        unsigned h, l;
        split_pack(zh[idx], zh[2048 + idx], h, l);
        Xuh[(size_t)ip*LCOLS + (bbase + bl)*CC + 1 + o] = h;
        Xul[(size_t)ip*LCOLS + (bbase + bl)*CC + 1 + o] = l;
    }
    if (tid < 32) {
        int b = bbase + tid;
        unsigned h, l;
        split_pack(x[(size_t)(b*TT + t)*NN + n0], x[(size_t)(b*TT + t)*NN + n0 + 1], h, l);
        Xuh[(size_t)ip*LCOLS + b*CC] = h;
        Xul[(size_t)ip*LCOLS + b*CC] = l;
    }
}

__global__ __launch_bounds__(256, 3) void update_epi_mma(
    const float* __restrict__ ub,
    float* __restrict__ out, const float* __restrict__ x, int t, int parity)
{
    extern __shared__ char smem[];
    unsigned short* xhp = (unsigned short*)smem;
    unsigned short* xlp = xhp + XQ;
    unsigned* WhB = (unsigned*)(xlp + XQ);
    unsigned* WlB = WhB + 2*8*72;
    float* sbias  = (float*)(WlB + 2*8*72);
    float* nes    = sbias + 2*64;

    int tid = threadIdx.x;
    int ip = blockIdx.x;
    int bh = blockIdx.y;
    int n0 = ip*2;
    int bbase = bh*32;
    size_t pb = (size_t)parity*2*WUSZ;

    const unsigned* Xh  = (const unsigned*)d_Xu;  const unsigned* Xl  = Xh  + (size_t)NP2*LCOLS;
    const unsigned* Y1h = (const unsigned*)d_Y1u; const unsigned* Y1l = Y1h + (size_t)NP2*LCOLS;
    const unsigned* Y2h = (const unsigned*)d_Y2u; const unsigned* Y2l = Y2h + (size_t)NP2*LCOLS;

    for (int e = tid; e < 32*CC; e += 256) {
        int bl = e / CC, i = e - (e/CC)*CC;
        size_t off = (size_t)ip*LCOLS + (bbase + bl)*CC + i;
        float x0, x1, y10, y11, y20, y21;
        unpack2(Xh[off],  Xl[off],  x0,  x1);
        unpack2(Y1h[off], Y1l[off], y10, y11);
        unpack2(Y2h[off], Y2l[off], y20, y21);
        int base0 = bl*STR + i;
        sp_store(xhp, xlp, base0,       x0);
        sp_store(xhp, xlp, base0 + 65,  y10);
        sp_store(xhp, xlp, base0 + 130, 2.f*y20 - x0);
        int base1 = 32*STR + base0;
        sp_store(xhp, xlp, base1,       x1);
        sp_store(xhp, xlp, base1 + 65,  y11);
        sp_store(xhp, xlp, base1 + 130, 2.f*y21 - x1);
    }
    for (int idx = tid; idx < 2*32*17; idx += 256) {
        int nd = idx / 544;
        int r = idx - nd*544;
        int bl = r / 17, k = r - bl*17;
        int pos = nd*32*STR + bl*STR + 195 + k;
        xhp[pos] = 0; xlp[pos] = 0;
    }
    if (tid < 32) {
        int nd = tid >> 4, d = tid & 15;
        nes[nd*16 + d] = d_ne_u[(size_t)(t*NN + n0 + nd)*DD + d];
    }
    __syncthreads();
    if (tid < 128) {
        int nd = tid >> 6, o = tid & 63;
        float s = 0.f;
#pragma unroll
        for (int d = 0; d < DD; d++) s += nes[nd*16 + d]*ub[d*OU + o];
        sbias[nd*64 + o] = s;
    }

    int wid = tid >> 5, lane = tid & 31;
    int nd = wid >> 2, w4 = wid & 3;
    int wn = w4*16;
    int grp = lane >> 2, tig = lane & 3;
    const unsigned short* xh = xhp + nd*32*STR;
    const unsigned short* xl = xlp + nd*32*STR;
    const unsigned* Wh = WhB + nd*576;
    const unsigned* Wl = WlB + nd*576;

    float acc[2][2][4];
#pragma unroll
    for (int i = 0; i < 2; i++)
#pragma unroll
        for (int j = 0; j < 2; j++)
#pragma unroll
            for (int c = 0; c < 4; c++) acc[i][j][c] = 0.f;

    for (int ch = 0; ch < 13; ch++) {
        {
            int snd = tid >> 7, sr2 = (tid >> 4) & 7, so4 = (tid & 15) << 2;
            size_t a = pb + ((size_t)(n0 + snd)*K2T + ch*8 + sr2)*OU + so4;
            *(uint4*)&WhB[snd*576 + sr2*72 + so4] = *(const uint4*)&d_Wu[a];
            *(uint4*)&WlB[snd*576 + sr2*72 + so4] = *(const uint4*)&d_Wu[WUSZ + a];
        }
        __syncthreads();

        unsigned bhf[2][2], blf[2][2];
#pragma unroll
        for (int nt = 0; nt < 2; nt++) {
            int o = wn + nt*8 + grp;
            bhf[nt][0] = Wh[tig*72 + o];     bhf[nt][1] = Wh[(tig+4)*72 + o];
            blf[nt][0] = Wl[tig*72 + o];     blf[nt][1] = Wl[(tig+4)*72 + o];
        }
        int kgA = ch*16 + 2*tig;
#pragma unroll
        for (int mt = 0; mt < 2; mt++) {
            int b0 = mt*16 + grp, b1 = b0 + 8;
            unsigned ah0 = *(const unsigned*)&xh[b0*STR + kgA];
            unsigned al0 = *(const unsigned*)&xl[b0*STR + kgA];
            unsigned ah1 = *(const unsigned*)&xh[b1*STR + kgA];
            unsigned al1 = *(const unsigned*)&xl[b1*STR + kgA];
            unsigned ah2 = *(const unsigned*)&xh[b0*STR + kgA + 8];
            unsigned al2 = *(const unsigned*)&xl[b0*STR + kgA + 8];
            unsigned ah3 = *(const unsigned*)&xh[b1*STR + kgA + 8];
            unsigned al3 = *(const unsigned*)&xl[b1*STR + kgA + 8];
#pragma unroll
            for (int nt = 0; nt < 2; nt++) {
                mma_bf16(acc[mt][nt][0], acc[mt][nt][1], acc[mt][nt][2], acc[mt][nt][3],
                         ah0, ah1, ah2, ah3, bhf[nt][0], bhf[nt][1]);
                mma_bf16(acc[mt][nt][0], acc[mt][nt][1], acc[mt][nt][2], acc[mt][nt][3],
                         ah0, ah1, ah2, ah3, blf[nt][0], blf[nt][1]);
                mma_bf16(acc[mt][nt][0], acc[mt][nt][1], acc[mt][nt][2], acc[mt][nt][3],
                         al0, al1, al2, al3, bhf[nt][0], bhf[nt][1]);
            }
        }
        __syncthreads();
    }

    float* zh = (float*)smem;
    int n = n0 + nd;
#pragma unroll
    for (int mt = 0; mt < 2; mt++) {
#pragma unroll
        for (int nt = 0; nt < 2; nt++) {
            int o0 = wn + nt*8 + tig*2;
#pragma unroll
            for (int c = 0; c < 4; c++) {
                int bl = mt*16 + grp + ((c >> 1) ? 8 : 0);
                int b = bbase + bl;
                int o = o0 + (c & 1);
                float hc = tanhf(acc[mt][nt][c] + sbias[nd*64 + o]);
                size_t idx = (size_t)(n*BB + b)*HH + o;
                float hv = d_h[idx];
                float rv = d_r[idx];
                float hn = rv*hv + (1.f - rv)*hc;
                d_h[idx] = hn;
                out[((size_t)(b*TT + t)*NN + n)*HH + o] = hn;
                zh[nd*2048 + bl*64 + o] = hn;
            }
        }
    }
    __syncthreads();

    if (t + 1 < TT) {
        unsigned* Xgh = (unsigned*)d_Xg;
        unsigned* Xgl = Xgh + (size_t)NP2*LCOLS;
        for (int idx = tid; idx < 2048; idx += 256) {
            int bl = idx >> 6, o = idx & 63;
            unsigned h, l;
            split_pack(zh[idx], zh[2048 + idx], h, l);
            Xgh[(size_t)ip*LCOLS + (bbase + bl)*CC + 1 + o] = h;
            Xgl[(size_t)ip*LCOLS + (bbase + bl)*CC + 1 + o] = l;
        }
        if (tid < 32) {
            int b = bbase + tid;
            unsigned h, l;
            split_pack(x[(size_t)(b*TT + t+1)*NN + n0], x[(size_t)(b*TT + t+1)*NN + n0 + 1], h, l);
            Xgh[(size_t)ip*LCOLS + b*CC] = h;
            Xgl[(size_t)ip*LCOLS + b*CC] = l;
        }
    }
}

// ---------------- host launcher (forked stream: wgen overlaps GEMMs) ----------------
extern "C" void kernel_launch(void* const* d_in, const int* in_sizes, int n_in,
                              void* d_out, int out_size)
{
    const float *x = nullptr, *nodeE = nullptr, *timeE = nullptr;
    const float *gW = nullptr, *gb = nullptr, *uW = nullptr, *ub = nullptr;
    const float *ln16[4] = {nullptr, nullptr, nullptr, nullptr};
    int nln = 0;
    for (int i = 0; i < n_in; i++) {
        const float* p = (const float*)d_in[i];
        switch (in_sizes[i]) {
            case 786432: x = p; break;
            case 16384:  nodeE = p; break;
            case 192:    timeE = p; break;
            case 399360: gW = p; break;
            case 2048:   gb = p; break;
            case 199680: uW = p; break;
            case 1024:   ub = p; break;
            case 16:     if (nln < 4) ln16[nln++] = p; break;
            default: break;
        }
    }
    const float* glg = ln16[0]; const float* glb = ln16[1];
    const float* ulg = ln16[2]; const float* ulb = ln16[3];
    float* out = (float*)d_out;

    cudaFuncSetAttribute(mma_gemm2,      cudaFuncAttributeMaxDynamicSharedMemorySize, GEMM_SMEM);
    cudaFuncSetAttribute(gate_epi_mma,   cudaFuncAttributeMaxDynamicSharedMemorySize, GATE_SMEM);
    cudaFuncSetAttribute(update_epi_mma, cudaFuncAttributeMaxDynamicSharedMemorySize, UPD_SMEM);

    dim3 egrid(NP2, 2);
    dim3 wgrid(NN/8, 4, 2);
    dim3 ggrid((LCOLS + 255)/256, NN/128);

    // side stream + events (created per call and leaked: kernel_launch runs only
    // for the correctness pass and the single graph-capture pass; no device memory)
    cudaStream_t s2;
    cudaStreamCreate(&s2);
    cudaEvent_t evNe, evW[TT], evS[TT];
    cudaEventCreateWithFlags(&evNe, cudaEventDisableTiming);
    for (int i = 0; i < TT; i++) {
        cudaEventCreateWithFlags(&evW[i], cudaEventDisableTiming);
        cudaEventCreateWithFlags(&evS[i], cudaEventDisableTiming);
    }

    // main stream work
    compute_ne_kernel<<<(TT*NN + 255)/256, 256>>>(nodeE, timeE, glg, glb, ulg, ulb);
    cudaEventRecord(evNe, 0);

    // fork: wgen(0) and wgen(1) overlap score/softmax/pack0
    cudaStreamWaitEvent(s2, evNe, 0);
    wgen_both<<<wgrid, 256, 0, s2>>>(gW, uW, 0, 0);
    cudaEventRecord(evW[0], s2);
    wgen_both<<<wgrid, 256, 0, s2>>>(gW, uW, 1, 1);
    cudaEventRecord(evW[1], s2);

    score_fused_kernel<<<dim3(8, 8, 2*TT), 256>>>(nodeE, timeE, glg, glb, ulg, ulb);
    softmax_kernel<<<dim3(128, TT, 2), 256>>>();
    zero_pack0_kernel<<<(NN*BB*HH + 255)/256, 256>>>(x);

    for (int t = 0; t < TT; t++) {
        int par = t & 1;
        mma_gemm2<<<ggrid, 256, GEMM_SMEM>>>(0, t, 0, 1);   // Y1g = Sg @ Xg
        mma_gemm2<<<ggrid, 256, GEMM_SMEM>>>(0, t, 1, 2);   // Y2g = Sg @ Y1g
        cudaStreamWaitEvent(0, evW[t], 0);
        gate_epi_mma<<<egrid, 256, GATE_SMEM>>>(gb, x, t, par);
        mma_gemm2<<<ggrid, 256, GEMM_SMEM>>>(1, t, 3, 4);   // Y1u = Su @ Xu
        mma_gemm2<<<ggrid, 256, GEMM_SMEM>>>(1, t, 4, 5);   // Y2u = Su @ Y1u
        update_epi_mma<<<egrid, 256, UPD_SMEM>>>(ub, out, x, t, par);
        cudaEventRecord(evS[t], 0);
        if (t + 2 < TT) {
            // wgen(t+2) reuses parity (t&1), last read by epilogues of step t (just enqueued)
            cudaStreamWaitEvent(s2, evS[t], 0);
            wgen_both<<<wgrid, 256, 0, s2>>>(gW, uW, t + 2, (t + 2) & 1);
            cudaEventRecord(evW[t + 2], s2);
        }
    }
    // s2 fully rejoined: evW[TT-1] was waited on the main stream at t = TT-1.
}